// round 15
// baseline (speedup 1.0000x reference)
#include <cuda_runtime.h>
#include <cuda_fp16.h>
#include <math.h>
#include <stdint.h>

#define Bb   4
#define Tt   1024
#define BT   4096          // Bb*Tt tokens
#define DM   768
#define DI   1536
#define NH   24
#define HD   64
#define DS   16
#define CD   1568          // D_INNER + 2*D_STATE
#define DPJ  3128          // 2*DI + 2*DS + NH
#define DIN  80
#define NCH  16            // scan chunks
#define CLEN 64            // steps per chunk
#define LEPS 1e-5f

// ---------------- scratch (device globals; no allocations allowed) ----------
__device__ float g_h  [BT*DM];
__device__ float g_hn [BT*DM];
__device__ float g_zx [2][BT*DPJ];
__device__ float g_xbc[2][BT*CD];
__device__ float g_dt [2][BT*NH];
__device__ float g_dA [2][BT*NH];
__device__ float g_y  [2][BT*DI];
__device__ float g_o  [2][BT*DM];
__device__ int   g_mask_kind;   // 0=int32, 1=float32, 2=uint8/bool
// chunked-scan scratch
__device__ float g_sloc[2][96*NCH*HD*DS];
__device__ float g_s0  [2][96*NCH*HD*DS];
__device__ float g_pl  [2][96*Tt];
// fp16 weight planes, transposed to [N,K]
__device__ __half g_wih[4][DPJ*DM], g_wil[4][DPJ*DM];
__device__ __half g_woh[4][DM*DI],  g_wol[4][DM*DI];
__device__ __half g_wpih[DM*DIN],   g_wpil[DM*DIN];
__device__ __half g_wpoh[DIN*DM],   g_wpol[DIN*DM];
// fp16 activation planes
__device__ __half g_hn16[BT*DM];
__device__ __half g_yn16[2][BT*DI];
__device__ __half g_x16 [BT*DIN];

// ---------------- generic helpers ----------------
__device__ __forceinline__ float block_sum(float v, float* sh) {
    int lane = threadIdx.x & 31, wid = threadIdx.x >> 5;
    #pragma unroll
    for (int o = 16; o > 0; o >>= 1) v += __shfl_xor_sync(0xffffffffu, v, o);
    if (lane == 0) sh[wid] = v;
    __syncthreads();
    int nw = (blockDim.x + 31) >> 5;
    if (threadIdx.x < 32) {
        float t = (threadIdx.x < nw) ? sh[threadIdx.x] : 0.f;
        #pragma unroll
        for (int o = 16; o > 0; o >>= 1) t += __shfl_xor_sync(0xffffffffu, t, o);
        if (threadIdx.x == 0) sh[0] = t;
    }
    __syncthreads();
    float r = sh[0];
    __syncthreads();
    return r;
}

__device__ __forceinline__ float rsqrt_acc(float a) {
    float r = rsqrtf(a);
    r = r * (1.5f - 0.5f * a * r * r);
    return r;
}

__device__ __forceinline__ float silu_f(float v) {
    return v / (1.f + expf(-v));
}

__device__ __forceinline__ uint32_t smem_u32(const void* p) {
    uint32_t a;
    asm("{ .reg .u64 t; cvta.to.shared.u64 t, %1; cvt.u32.u64 %0, t; }" : "=r"(a) : "l"(p));
    return a;
}

// ---------------- tensor-core GEMM (fp16 x2), batched over gridDim.z --------
// Per z: A = A16 + z*szA, W = Wh/Wl + z*szW, bias + z*szB, C + z*szC.
#define SAS   40                // half row stride in smem (80 bytes)
#define PLB   10240             // bytes per plane: 128*40*2
#define BUFB  (3*PLB)           // A, Wh, Wl = 30720 bytes per buffer
#define TG_SMEM (2*BUFB)        // 61440

#define MMA16816(acc, a, b) \
    asm volatile("mma.sync.aligned.m16n8k16.row.col.f32.f16.f16.f32 " \
        "{%0,%1,%2,%3},{%4,%5,%6,%7},{%8,%9},{%0,%1,%2,%3};" \
        : "+f"((acc)[0]), "+f"((acc)[1]), "+f"((acc)[2]), "+f"((acc)[3]) \
        : "r"((a)[0]), "r"((a)[1]), "r"((a)[2]), "r"((a)[3]), \
          "r"((b)[0]), "r"((b)[1]))

#define LDSM4(r, addr) \
    asm volatile("ldmatrix.sync.aligned.m8n8.x4.shared.b16 {%0,%1,%2,%3}, [%4];" \
        : "=r"((r)[0]), "=r"((r)[1]), "=r"((r)[2]), "=r"((r)[3]) : "r"(addr))

__device__ __forceinline__ void cpa16(uint32_t s, const void* g, int szr) {
    asm volatile("cp.async.cg.shared.global [%0], [%1], 16, %2;"
                 :: "r"(s), "l"(__cvta_generic_to_global(g)), "r"(szr) : "memory");
}

__global__ __launch_bounds__(256, 2)
void tgemm_k(const __half* __restrict__ A16g, size_t szA,
             const __half* __restrict__ Whg, const __half* __restrict__ Wlg, size_t szW,
             const float* __restrict__ biasg, size_t szB,
             float* __restrict__ Cg, size_t szC,
             int N, int K, int ldC) {
    extern __shared__ __align__(16) char smraw[];
    const uint32_t sb = smem_u32(smraw);
    const int z = blockIdx.z;
    const __half* A16 = A16g + (size_t)z * szA;
    const __half* Wh  = Whg  + (size_t)z * szW;
    const __half* Wl  = Wlg  + (size_t)z * szW;
    const float*  bias = biasg ? biasg + (size_t)z * szB : nullptr;
    float* C = Cg + (size_t)z * szC;
    const int tid  = threadIdx.x;
    const int lane = tid & 31, warp = tid >> 5;
    const int wr = warp >> 2, wc = warp & 3;
    const int gid = lane >> 2, tq = lane & 3;
    const int row0 = blockIdx.y * 128, n0 = blockIdx.x * 128;

    const int rw = lane & 7;
    const uint32_t aoff = (uint32_t)(((rw + ((lane >> 3) & 1) * 8) * SAS + (lane >> 4) * 8) * 2);
    const uint32_t boff = (uint32_t)(((rw + (lane >> 4) * 8) * SAS + ((lane >> 3) & 1) * 8) * 2);

    float acc[4][4][4];
    #pragma unroll
    for (int mi = 0; mi < 4; mi++)
        #pragma unroll
        for (int ni = 0; ni < 4; ni++)
            #pragma unroll
            for (int e = 0; e < 4; e++) acc[mi][ni][e] = 0.f;

    const int nst = (K + 31) >> 5;

    auto issue = [&](int s, int buf) {
        const int k0 = s * 32;
        const uint32_t base = sb + buf * BUFB;
        #pragma unroll
        for (int i = 0; i < 6; i++) {
            int task = i * 256 + tid;          // 0..1535
            int plane = task >> 9;             // 0:A 1:Wh 2:Wl
            int idx = task & 511;
            int r = idx >> 2, c16 = idx & 3;
            uint32_t dst = base + plane * PLB + (uint32_t)((r * SAS + c16 * 8) * 2);
            int k = k0 + c16 * 8;
            const __half* g;
            int sz = 16;
            if (plane == 0) {
                g = A16 + (size_t)(row0 + r) * K + k;
                if (k + 8 > K) sz = 0;
            } else {
                int n = n0 + r;
                g = (plane == 2 ? Wl : Wh) + (size_t)n * K + k;
                if (k + 8 > K || n >= N) sz = 0;
            }
            if (sz == 0) g = A16;
            cpa16(dst, g, sz);
        }
        asm volatile("cp.async.commit_group;" ::: "memory");
    };

    auto compute = [&](int buf) {
        const uint32_t sA = sb + buf * BUFB;
        const uint32_t sW = sA + PLB;
        #pragma unroll
        for (int kk = 0; kk < 32; kk += 16) {
            uint32_t ah[4][4];
            #pragma unroll
            for (int mi = 0; mi < 4; mi++) {
                uint32_t ab = sA + (uint32_t)(((wr * 64 + mi * 16) * SAS + kk) * 2);
                LDSM4(ah[mi], ab + aoff);
            }
            #pragma unroll
            for (int pr = 0; pr < 2; pr++) {
                uint32_t bh2[4], bl2[4];
                uint32_t bb = sW + (uint32_t)(((wc * 32 + pr * 16) * SAS + kk) * 2);
                LDSM4(bh2, bb + boff);
                LDSM4(bl2, bb + PLB + boff);
                #pragma unroll
                for (int q = 0; q < 2; q++) {
                    int ni = pr * 2 + q;
                    #pragma unroll
                    for (int mi = 0; mi < 4; mi++) {
                        MMA16816(acc[mi][ni], ah[mi], &bh2[q * 2]);
                        MMA16816(acc[mi][ni], ah[mi], &bl2[q * 2]);
                    }
                }
            }
        }
    };

    issue(0, 0);
    for (int s = 0; s < nst; s++) {
        if (s + 1 < nst) {
            issue(s + 1, (s + 1) & 1);
            asm volatile("cp.async.wait_group 1;" ::: "memory");
        } else {
            asm volatile("cp.async.wait_group 0;" ::: "memory");
        }
        __syncthreads();
        compute(s & 1);
        __syncthreads();
    }

    #pragma unroll
    for (int mi = 0; mi < 4; mi++) {
        int row = row0 + wr * 64 + mi * 16 + gid;
        #pragma unroll
        for (int ni = 0; ni < 4; ni++) {
            int col = n0 + wc * 32 + ni * 8 + tq * 2;
            if (col < N) {
                float b0 = bias ? bias[col]     : 0.f;
                float b1 = bias ? bias[col + 1] : 0.f;
                float* c0 = C + (size_t)row * ldC + col;
                c0[0] = acc[mi][ni][0] + b0;
                c0[1] = acc[mi][ni][1] + b1;
                float* c1 = C + (size_t)(row + 8) * ldC + col;
                c1[0] = acc[mi][ni][2] + b0;
                c1[1] = acc[mi][ni][3] + b1;
            }
        }
    }
}

// ---------------- weight convert+transpose: src[R,C] fp32 -> dst[C,R] hi/lo -
__global__ void convert_wt_k(const float* __restrict__ src,
                             __half* __restrict__ dhi, __half* __restrict__ dlo,
                             int R, int C) {
    __shared__ float tile[32][33];
    int c0 = blockIdx.x * 32, r0 = blockIdx.y * 32;
    int x = c0 + threadIdx.x;
    #pragma unroll
    for (int j = threadIdx.y; j < 32; j += 8) {
        int r = r0 + j;
        tile[j][threadIdx.x] = (r < R && x < C) ? src[(size_t)r * C + x] : 0.f;
    }
    __syncthreads();
    int xr = r0 + threadIdx.x;
    #pragma unroll
    for (int j = threadIdx.y; j < 32; j += 8) {
        int c = c0 + j;
        if (c < C && xr < R) {
            float v = tile[threadIdx.x][j];
            __half h = __float2half_rn(v);
            __half l = __float2half_rn(v - __half2float(h));
            dhi[(size_t)c * R + xr] = h;
            dlo[(size_t)c * R + xr] = l;
        }
    }
}

// ---------------- activation convert: fp32 -> fp16 --------------------------
__global__ void convert_a_k(const float* __restrict__ src,
                            __half* __restrict__ dst, int n) {
    int i = blockIdx.x * 256 + threadIdx.x;
    if (i < n) dst[i] = __float2half_rn(src[i]);
}

// ---------------- mask dtype detector -----------
__global__ void detect_mask_k(const unsigned int* __restrict__ m) {
    __shared__ int s_ni, s_nf;
    if (threadIdx.x == 0) { s_ni = 0; s_nf = 0; }
    __syncthreads();
    int ni = 0, nf = 0;
    for (int i = threadIdx.x; i < 1024; i += blockDim.x) {
        unsigned w = m[i];
        if (w != 0u && w != 1u)           ni = 1;
        if (w != 0u && w != 0x3F800000u)  nf = 1;
    }
    if (ni) atomicOr(&s_ni, 1);
    if (nf) atomicOr(&s_nf, 1);
    __syncthreads();
    if (threadIdx.x == 0)
        g_mask_kind = (!s_ni) ? 0 : ((!s_nf) ? 1 : 2);
}

__global__ void mask_apply_k(const void* __restrict__ maskp,
                             const float* __restrict__ mask_token) {
    int bt = blockIdx.x;
    int kind = g_mask_kind;
    bool is;
    if (kind == 0)      is = ((const int*)maskp)[bt] != 0;
    else if (kind == 1) is = ((const float*)maskp)[bt] != 0.f;
    else                is = ((const unsigned char*)maskp)[bt] != 0;
    if (is) g_h[bt * DM + threadIdx.x] = mask_token[threadIdx.x];
}

// ---------------- LayerNorm(768) with optional fused residual add -----------
__global__ void layernorm_k(float* __restrict__ hbuf,
                            const float* __restrict__ o0, const float* __restrict__ o1,
                            const float* __restrict__ w, const float* __restrict__ b,
                            float* __restrict__ out, __half* __restrict__ out16,
                            int wb) {
    __shared__ float sh[32];
    int row = blockIdx.x;
    float* x = hbuf + (size_t)row * DM;
    int t = threadIdx.x;
    float v0 = x[t], v1 = x[t + 256], v2 = x[t + 512];
    if (o0) {
        const float* a = o0 + (size_t)row * DM;
        const float* c = o1 + (size_t)row * DM;
        v0 += a[t]       + c[t];
        v1 += a[t + 256] + c[t + 256];
        v2 += a[t + 512] + c[t + 512];
        if (wb) { x[t] = v0; x[t + 256] = v1; x[t + 512] = v2; }
    }
    float S  = block_sum(v0 + v1 + v2, sh);
    float mu = S * (1.f / DM);
    float d0 = v0 - mu, d1 = v1 - mu, d2 = v2 - mu;
    float S2 = block_sum(d0 * d0 + d1 * d1 + d2 * d2, sh);
    float inv = rsqrt_acc(S2 * (1.f / DM) + LEPS);
    float r0 = d0 * inv * w[t]       + b[t];
    float r1 = d1 * inv * w[t + 256] + b[t + 256];
    float r2 = d2 * inv * w[t + 512] + b[t + 512];
    if (out) {
        float* o = out + (size_t)row * DM;
        o[t] = r0; o[t + 256] = r1; o[t + 512] = r2;
    }
    if (out16) {
        __half* o = out16 + (size_t)row * DM;
        o[t]       = __float2half_rn(r0);
        o[t + 256] = __float2half_rn(r1);
        o[t + 512] = __float2half_rn(r2);
    }
}

// ---------------- depthwise causal conv7 + silu (per direction) -------------
__global__ void conv_silu_k(const float* __restrict__ cw, const float* __restrict__ cb,
                            int l, int d) {
    int idx = blockIdx.x * 256 + threadIdx.x;
    if (idx >= BT * CD) return;
    int c = idx % CD;
    int btt = idx / CD;
    int b = btt >> 10, t = btt & 1023;
    const float* w = cw + ((size_t)(l * 2 + d) * CD + c) * 7;
    float acc = cb[(l * 2 + d) * CD + c];
    const float* src = g_zx[d];
    if (d == 0) {
        #pragma unroll
        for (int k = 0; k < 7; k++) {
            int tt = t - 6 + k;
            if (tt >= 0) acc = fmaf(w[k], src[(size_t)(b * Tt + tt) * DPJ + 1536 + c], acc);
        }
    } else {
        #pragma unroll
        for (int k = 0; k < 7; k++) {
            int tt = t + 6 - k;
            if (tt < Tt) acc = fmaf(w[k], src[(size_t)(b * Tt + tt) * DPJ + 1536 + c], acc);
        }
    }
    g_xbc[d][idx] = silu_f(acc);
}

// ---------------- dt: softplus + dA (per direction) --------------------------
__global__ void dt_prep_k(const float* __restrict__ dt_bias, const float* __restrict__ A_log,
                          int l, int d) {
    int idx = blockIdx.x * 256 + threadIdx.x;
    int h = idx % NH;
    int bt = idx / NH;
    float raw = g_zx[d][(size_t)bt * DPJ + 3104 + h] + dt_bias[(l * 2 + d) * NH + h];
    float dt = (raw > 20.f) ? raw : log1pf(expf(raw));
    float a = -expf(A_log[(l * 2 + d) * NH + h]);
    g_dt[d][idx] = dt;
    g_dA[d][idx] = expf(a * dt);
}

// ---------------- chunked scan pass 1: local scans per chunk -----------------
__global__ void scan1_k(const float* __restrict__ Dp, int l, int d) {
    const int blk = blockIdx.x;
    const int bh = blk >> 4, c = blk & (NCH - 1);
    const int b = bh / NH, hh = bh % NH;
    const int p = threadIdx.x;
    const float* __restrict__ xbc = g_xbc[d];
    const float* __restrict__ dtp = g_dt[d];
    const float* __restrict__ dAp = g_dA[d];
    float* __restrict__ yb = g_y[d];
    float* __restrict__ plb = &g_pl[d][bh * Tt];
    const float Dc = Dp[(l * 2 + d) * NH + hh];
    float s[16];
    #pragma unroll
    for (int n = 0; n < 16; n++) s[n] = 0.f;
    float pl = 1.f;
    for (int il = 0; il < CLEN; il++) {
        int i = c * CLEN + il;
        int t = d ? (Tt - 1 - i) : i;
        int bt = b * Tt + t;
        const float* row = xbc + (size_t)bt * CD;
        float xv = row[hh * HD + p];
        float dt = dtp[bt * NH + hh];
        float dA = dAp[bt * NH + hh];
        float Bv[16], Cv[16];
        #pragma unroll
        for (int q = 0; q < 4; q++) {
            *(float4*)&Bv[q * 4] = *(const float4*)(row + 1536 + q * 4);
            *(float4*)&Cv[q * 4] = *(const float4*)(row + 1552 + q * 4);
        }
        float c0 = dt * xv;
        float a0 = 0.f, a1 = 0.f, a2 = 0.f, a3 = 0.f;
        #pragma unroll
        for (int n = 0; n < 16; n += 4) {
            s[n+0] = fmaf(s[n+0], dA, c0 * Bv[n+0]); a0 = fmaf(s[n+0], Cv[n+0], a0);
            s[n+1] = fmaf(s[n+1], dA, c0 * Bv[n+1]); a1 = fmaf(s[n+1], Cv[n+1], a1);
            s[n+2] = fmaf(s[n+2], dA, c0 * Bv[n+2]); a2 = fmaf(s[n+2], Cv[n+2], a2);
            s[n+3] = fmaf(s[n+3], dA, c0 * Bv[n+3]); a3 = fmaf(s[n+3], Cv[n+3], a3);
        }
        yb[(size_t)bt * DI + hh * HD + p] = (a0 + a1) + (a2 + a3) + Dc * xv;
        pl *= dA;
        if (p == 0) plb[i] = pl;
    }
    float* dst = &g_sloc[d][(size_t)((bh * NCH + c) * HD + p) * DS];
    #pragma unroll
    for (int q = 0; q < 4; q++)
        *(float4*)(dst + q * 4) = make_float4(s[q*4], s[q*4+1], s[q*4+2], s[q*4+3]);
}

// ---------------- chunked scan pass 2: combine chunk states ------------------
__global__ void scan2_k(int d) {
    const int bh = blockIdx.x;
    const int tid = threadIdx.x;
    const int p = tid >> 4, n = tid & 15;
    const float* __restrict__ plb = &g_pl[d][bh * Tt];
    float S = 0.f;
    #pragma unroll
    for (int c = 0; c < NCH; c++) {
        size_t base = (size_t)((bh * NCH + c) * HD + p) * DS + n;
        g_s0[d][base] = S;
        float P  = plb[c * CLEN + CLEN - 1];
        float sl = g_sloc[d][base];
        S = S * P + sl;
    }
}

// ---------------- chunked scan pass 3: apply cross-chunk correction ----------
__global__ void scan3_k(int d) {
    const int blk = blockIdx.x;
    const int bh = blk >> 4, c = blk & (NCH - 1);
    if (c == 0) return;
    const int b = bh / NH, hh = bh % NH;
    const int p = threadIdx.x;
    const float* __restrict__ xbc = g_xbc[d];
    const float* __restrict__ plb = &g_pl[d][bh * Tt];
    float* __restrict__ yb = g_y[d];
    float S[16];
    const float* sp = &g_s0[d][(size_t)((bh * NCH + c) * HD + p) * DS];
    #pragma unroll
    for (int q = 0; q < 4; q++) {
        float4 v = *(const float4*)(sp + q * 4);
        S[q*4] = v.x; S[q*4+1] = v.y; S[q*4+2] = v.z; S[q*4+3] = v.w;
    }
    for (int il = 0; il < CLEN; il++) {
        int i = c * CLEN + il;
        int t = d ? (Tt - 1 - i) : i;
        int bt = b * Tt + t;
        const float* row = xbc + (size_t)bt * CD;
        float Cv[16];
        #pragma unroll
        for (int q = 0; q < 4; q++)
            *(float4*)&Cv[q * 4] = *(const float4*)(row + 1552 + q * 4);
        float pl = plb[i];
        float d0 = 0.f, d1 = 0.f;
        #pragma unroll
        for (int n = 0; n < 16; n += 2) {
            d0 = fmaf(Cv[n], S[n], d0);
            d1 = fmaf(Cv[n+1], S[n+1], d1);
        }
        yb[(size_t)bt * DI + hh * HD + p] += pl * (d0 + d1);
    }
}

// ---------------- gated RMS norm over 1536 -> fp16 plane (per direction) ----
__global__ void gated_rms_k(const float* __restrict__ ssm_w, int l, int d) {
    __shared__ float sh[32];
    int row = blockIdx.x;
    const float* y = g_y[d] + (size_t)row * DI;
    const float* z = g_zx[d] + (size_t)row * DPJ;
    __half* out = g_yn16[d] + (size_t)row * DI;
    const float* w = ssm_w + (l * 2 + d) * DI;
    int t = threadIdx.x;
    float g[6], s2 = 0.f;
    #pragma unroll
    for (int i = 0; i < 6; i++) {
        int c = t + 256 * i;
        float gv = y[c] * silu_f(z[c]);
        g[i] = gv;
        s2 += gv * gv;
    }
    float S2 = block_sum(s2, sh);
    float inv = rsqrt_acc(S2 * (1.f / DI) + LEPS);
    #pragma unroll
    for (int i = 0; i < 6; i++) {
        int c = t + 256 * i;
        out[c] = __float2half_rn(g[i] * inv * w[c]);
    }
}

// ---------------- stream context (3 streams) --------------------------------
struct StreamCtx {
    cudaStream_t s0, s1, s2;
    cudaEvent_t evF, evP, evPO;
    cudaEvent_t evCI[4], evCO[4];
    cudaEvent_t evL[2], evI[2], evY0[2], evY1[2], evO[2];
    int ok;
};
static StreamCtx g_sc = {};

static void sc_init() {
    if (g_sc.ok) return;
    cudaStreamCreateWithFlags(&g_sc.s0, cudaStreamNonBlocking);
    cudaStreamCreateWithFlags(&g_sc.s1, cudaStreamNonBlocking);
    cudaStreamCreateWithFlags(&g_sc.s2, cudaStreamNonBlocking);
    cudaEventCreateWithFlags(&g_sc.evF,  cudaEventDisableTiming);
    cudaEventCreateWithFlags(&g_sc.evP,  cudaEventDisableTiming);
    cudaEventCreateWithFlags(&g_sc.evPO, cudaEventDisableTiming);
    for (int i = 0; i < 4; i++) {
        cudaEventCreateWithFlags(&g_sc.evCI[i], cudaEventDisableTiming);
        cudaEventCreateWithFlags(&g_sc.evCO[i], cudaEventDisableTiming);
    }
    for (int i = 0; i < 2; i++) {
        cudaEventCreateWithFlags(&g_sc.evL[i],  cudaEventDisableTiming);
        cudaEventCreateWithFlags(&g_sc.evI[i],  cudaEventDisableTiming);
        cudaEventCreateWithFlags(&g_sc.evY0[i], cudaEventDisableTiming);
        cudaEventCreateWithFlags(&g_sc.evY1[i], cudaEventDisableTiming);
        cudaEventCreateWithFlags(&g_sc.evO[i],  cudaEventDisableTiming);
    }
    g_sc.ok = 1;
}

// ---------------- launcher ---------------------------------------------------
extern "C" void kernel_launch(void* const* d_in, const int* in_sizes, int n_in,
                              void* d_out, int out_size) {
    const float* x          = (const float*)d_in[0];
    const void*  maskp      = d_in[1];
    const float* proj_in_w  = (const float*)d_in[2];
    const float* proj_in_b  = (const float*)d_in[3];
    const float* mask_token = (const float*)d_in[4];
    const float* ln_w       = (const float*)d_in[5];
    const float* ln_b       = (const float*)d_in[6];
    const float* in_proj_w  = (const float*)d_in[7];
    const float* in_proj_b  = (const float*)d_in[8];
    const float* conv_w     = (const float*)d_in[9];
    const float* conv_b     = (const float*)d_in[10];
    const float* dt_bias    = (const float*)d_in[11];
    const float* A_log      = (const float*)d_in[12];
    const float* Dp         = (const float*)d_in[13];
    const float* ssm_w      = (const float*)d_in[14];
    const float* out_proj_w = (const float*)d_in[15];
    const float* fn_w       = (const float*)d_in[16];
    const float* fn_b       = (const float*)d_in[17];
    const float* proj_out_w = (const float*)d_in[18];
    const float* proj_out_b = (const float*)d_in[19];
    float* out = (float*)d_out;

    sc_init();
    cudaStream_t S0 = g_sc.s0, S1 = g_sc.s1, S2 = g_sc.s2;
    cudaStream_t STD = (cudaStream_t)0;

    float *p_h, *p_hn, *p_zx, *p_o;
    __half *p_wih, *p_wil, *p_woh, *p_wol, *p_wpih, *p_wpil, *p_wpoh, *p_wpol;
    __half *p_hn16, *p_yn16, *p_x16;
    cudaGetSymbolAddress((void**)&p_h,    g_h);
    cudaGetSymbolAddress((void**)&p_hn,   g_hn);
    cudaGetSymbolAddress((void**)&p_zx,   g_zx);
    cudaGetSymbolAddress((void**)&p_o,    g_o);
    cudaGetSymbolAddress((void**)&p_wih,  g_wih);
    cudaGetSymbolAddress((void**)&p_wil,  g_wil);
    cudaGetSymbolAddress((void**)&p_woh,  g_woh);
    cudaGetSymbolAddress((void**)&p_wol,  g_wol);
    cudaGetSymbolAddress((void**)&p_wpih, g_wpih);
    cudaGetSymbolAddress((void**)&p_wpil, g_wpil);
    cudaGetSymbolAddress((void**)&p_wpoh, g_wpoh);
    cudaGetSymbolAddress((void**)&p_wpol, g_wpol);
    cudaGetSymbolAddress((void**)&p_hn16, g_hn16);
    cudaGetSymbolAddress((void**)&p_yn16, g_yn16);
    cudaGetSymbolAddress((void**)&p_x16,  g_x16);

    cudaFuncSetAttribute(tgemm_k, cudaFuncAttributeMaxDynamicSharedMemorySize, TG_SMEM);

    dim3 tb(32, 8);

    // ---- fork from capture stream
    detect_mask_k<<<1, 256, 0, STD>>>((const unsigned int*)maskp);
    cudaEventRecord(g_sc.evF, STD);
    cudaStreamWaitEvent(S0, g_sc.evF, 0);
    cudaStreamWaitEvent(S1, g_sc.evF, 0);
    cudaStreamWaitEvent(S2, g_sc.evF, 0);

    // ---- S2: weight conversions (layer-0 in_proj first)
    for (int i = 0; i < 2; i++) {
        convert_wt_k<<<dim3((DPJ + 31) / 32, (DM + 31) / 32), tb, 0, S2>>>(
            in_proj_w + (size_t)i * DM * DPJ,
            p_wih + (size_t)i * DPJ * DM, p_wil + (size_t)i * DPJ * DM, DM, DPJ);
        cudaEventRecord(g_sc.evCI[i], S2);
    }
    for (int i = 0; i < 2; i++) {
        convert_wt_k<<<dim3((DM + 31) / 32, (DI + 31) / 32), tb, 0, S2>>>(
            out_proj_w + (size_t)i * DI * DM,
            p_woh + (size_t)i * DM * DI, p_wol + (size_t)i * DM * DI, DI, DM);
        cudaEventRecord(g_sc.evCO[i], S2);
    }
    for (int i = 2; i < 4; i++) {
        convert_wt_k<<<dim3((DPJ + 31) / 32, (DM + 31) / 32), tb, 0, S2>>>(
            in_proj_w + (size_t)i * DM * DPJ,
            p_wih + (size_t)i * DPJ * DM, p_wil + (size_t)i * DPJ * DM, DM, DPJ);
        cudaEventRecord(g_sc.evCI[i], S2);
    }
    for (int i = 2; i < 4; i++) {
        convert_wt_k<<<dim3((DM + 31) / 32, (DI + 31) / 32), tb, 0, S2>>>(
            out_proj_w + (size_t)i * DI * DM,
            p_woh + (size_t)i * DM * DI, p_wol + (size_t)i * DM * DI, DI, DM);
        cudaEventRecord(g_sc.evCO[i], S2);
    }
    convert_wt_k<<<dim3((DIN + 31) / 32, (DM + 31) / 32), tb, 0, S2>>>(
        proj_out_w, p_wpoh, p_wpol, DM, DIN);
    cudaEventRecord(g_sc.evPO, S2);

    // ---- S0: proj_in path
    convert_wt_k<<<dim3((DM + 31) / 32, (DIN + 31) / 32), tb, 0, S0>>>(proj_in_w, p_wpih, p_wpil, DIN, DM);
    convert_a_k<<<(BT * DIN + 255) / 256, 256, 0, S0>>>(x, p_x16, BT * DIN);
    tgemm_k<<<dim3(DM / 128, BT / 128, 1), 256, TG_SMEM, S0>>>(
        p_x16, 0, p_wpih, p_wpil, 0, proj_in_b, 0, p_h, 0, DM, DIN, DM);
    mask_apply_k<<<BT, DM, 0, S0>>>(maskp, mask_token);
    cudaEventRecord(g_sc.evP, S0);

    cudaStreamWaitEvent(STD, g_sc.evP, 0);

    for (int l = 0; l < 2; l++) {
        layernorm_k<<<BT, 256, 0, STD>>>(
            p_h,
            l ? p_o : nullptr, l ? p_o + (size_t)BT * DM : nullptr,
            ln_w + l * DM, ln_b + l * DM, nullptr, p_hn16, 1);
        cudaEventRecord(g_sc.evL[l], STD);

        // ---- batched in_proj (both directions, one launch) on S0
        cudaStreamWaitEvent(S0, g_sc.evL[l], 0);
        cudaStreamWaitEvent(S0, g_sc.evCI[l * 2 + 0], 0);
        cudaStreamWaitEvent(S0, g_sc.evCI[l * 2 + 1], 0);
        tgemm_k<<<dim3((DPJ + 127) / 128, BT / 128, 2), 256, TG_SMEM, S0>>>(
            p_hn16, 0,
            p_wih + (size_t)(l * 2) * DPJ * DM,
            p_wil + (size_t)(l * 2) * DPJ * DM, (size_t)DPJ * DM,
            in_proj_b + (size_t)(l * 2) * DPJ, DPJ,
            p_zx, (size_t)BT * DPJ, DPJ, DM, DPJ);
        cudaEventRecord(g_sc.evI[l], S0);

        // ---- chain d0 on S1
        cudaStreamWaitEvent(S1, g_sc.evI[l], 0);
        conv_silu_k<<<(BT * CD + 255) / 256, 256, 0, S1>>>(conv_w, conv_b, l, 0);
        dt_prep_k<<<BT * NH / 256, 256, 0, S1>>>(dt_bias, A_log, l, 0);
        scan1_k<<<96 * NCH, HD, 0, S1>>>(Dp, l, 0);
        scan2_k<<<96, HD * DS, 0, S1>>>(0);
        scan3_k<<<96 * NCH, HD, 0, S1>>>(0);
        gated_rms_k<<<BT, 256, 0, S1>>>(ssm_w, l, 0);
        cudaEventRecord(g_sc.evY0[l], S1);

        // ---- chain d1 on S2
        cudaStreamWaitEvent(S2, g_sc.evI[l], 0);
        conv_silu_k<<<(BT * CD + 255) / 256, 256, 0, S2>>>(conv_w, conv_b, l, 1);
        dt_prep_k<<<BT * NH / 256, 256, 0, S2>>>(dt_bias, A_log, l, 1);
        scan1_k<<<96 * NCH, HD, 0, S2>>>(Dp, l, 1);
        scan2_k<<<96, HD * DS, 0, S2>>>(1);
        scan3_k<<<96 * NCH, HD, 0, S2>>>(1);
        gated_rms_k<<<BT, 256, 0, S2>>>(ssm_w, l, 1);
        cudaEventRecord(g_sc.evY1[l], S2);

        // ---- batched out_proj (both directions, one launch) on S0
        cudaStreamWaitEvent(S0, g_sc.evY0[l], 0);
        cudaStreamWaitEvent(S0, g_sc.evY1[l], 0);
        cudaStreamWaitEvent(S0, g_sc.evCO[l * 2 + 0], 0);
        cudaStreamWaitEvent(S0, g_sc.evCO[l * 2 + 1], 0);
        tgemm_k<<<dim3(DM / 128, BT / 128, 2), 256, TG_SMEM, S0>>>(
            p_yn16, (size_t)BT * DI,
            p_woh + (size_t)(l * 2) * DM * DI,
            p_wol + (size_t)(l * 2) * DM * DI, (size_t)DM * DI,
            nullptr, 0,
            p_o, (size_t)BT * DM, DM, DI, DM);
        cudaEventRecord(g_sc.evO[l], S0);

        cudaStreamWaitEvent(STD, g_sc.evO[l], 0);
    }

    // outputs: hidden = LN(h + o0 + o1, final); pred = hidden16 @ proj_out + b
    const int PRED = BT * DIN, HID = BT * DM;
    float* predp = nullptr;
    float* hidp  = nullptr;
    if (out_size >= PRED + HID)      { predp = out; hidp = out + PRED; }
    else if (out_size == PRED)       { predp = out; }
    else                             { hidp = out; }

    layernorm_k<<<BT, 256, 0, STD>>>(
        p_h, p_o, p_o + (size_t)BT * DM,
        fn_w, fn_b, hidp ? hidp : p_hn, p_hn16, 0);
    if (predp) {
        cudaStreamWaitEvent(STD, g_sc.evPO, 0);
        tgemm_k<<<dim3((DIN + 127) / 128, BT / 128, 1), 256, TG_SMEM, STD>>>(
            p_hn16, 0, p_wpoh, p_wpol, 0, proj_out_b, 0, predp, 0, DIN, DM, DIN);
    }
}

// round 16
// speedup vs baseline: 1.0558x; 1.0558x over previous
#include <cuda_runtime.h>
#include <cuda_fp16.h>
#include <math.h>
#include <stdint.h>

#define Bb   4
#define Tt   1024
#define BT   4096          // Bb*Tt tokens
#define DM   768
#define DI   1536
#define NH   24
#define HD   64
#define DS   16
#define CD   1568          // D_INNER + 2*D_STATE
#define DPJ  3128          // 2*DI + 2*DS + NH
#define DIN  80
#define NCH  16            // scan chunks
#define CLEN 64            // steps per chunk
#define NCONV ((BT*CD + 255) / 256)   // 25088 conv blocks
#define NDT   (BT*NH / 256)           // 384 dt blocks
#define LEPS 1e-5f

// ---------------- scratch (device globals; no allocations allowed) ----------
__device__ float g_h  [BT*DM];
__device__ float g_hn [BT*DM];
__device__ float g_zx [2][BT*DPJ];
__device__ float g_xbc[2][BT*CD];
__device__ float g_dt [2][BT*NH];
__device__ float g_dA [2][BT*NH];
__device__ float g_y  [2][BT*DI];
__device__ float g_o  [2][BT*DM];
__device__ int   g_mask_kind;   // 0=int32, 1=float32, 2=uint8/bool
// chunked-scan scratch
__device__ float g_sloc[2][96*NCH*HD*DS];
__device__ float g_s0  [2][96*NCH*HD*DS];
__device__ float g_pl  [2][96*Tt];
// fp16 weight planes, transposed to [N,K]
__device__ __half g_wih[4][DPJ*DM], g_wil[4][DPJ*DM];
__device__ __half g_woh[4][DM*DI],  g_wol[4][DM*DI];
__device__ __half g_wpih[DM*DIN],   g_wpil[DM*DIN];
__device__ __half g_wpoh[DIN*DM],   g_wpol[DIN*DM];
// fp16 activation planes
__device__ __half g_hn16[BT*DM];
__device__ __half g_yn16[2][BT*DI];
__device__ __half g_x16 [BT*DIN];

// ---------------- generic helpers ----------------
__device__ __forceinline__ float block_sum(float v, float* sh) {
    int lane = threadIdx.x & 31, wid = threadIdx.x >> 5;
    #pragma unroll
    for (int o = 16; o > 0; o >>= 1) v += __shfl_xor_sync(0xffffffffu, v, o);
    if (lane == 0) sh[wid] = v;
    __syncthreads();
    int nw = (blockDim.x + 31) >> 5;
    if (threadIdx.x < 32) {
        float t = (threadIdx.x < nw) ? sh[threadIdx.x] : 0.f;
        #pragma unroll
        for (int o = 16; o > 0; o >>= 1) t += __shfl_xor_sync(0xffffffffu, t, o);
        if (threadIdx.x == 0) sh[0] = t;
    }
    __syncthreads();
    float r = sh[0];
    __syncthreads();
    return r;
}

__device__ __forceinline__ float rsqrt_acc(float a) {
    float r = rsqrtf(a);
    r = r * (1.5f - 0.5f * a * r * r);
    return r;
}

__device__ __forceinline__ float silu_f(float v) {
    return v / (1.f + expf(-v));
}

__device__ __forceinline__ uint32_t smem_u32(const void* p) {
    uint32_t a;
    asm("{ .reg .u64 t; cvta.to.shared.u64 t, %1; cvt.u32.u64 %0, t; }" : "=r"(a) : "l"(p));
    return a;
}

// ---------------- tensor-core GEMM (fp16 x2: A16 @ (Wh+Wl)^T) ---------------
#define SAS   40                // half row stride in smem (80 bytes)
#define PLB   10240             // bytes per plane: 128*40*2
#define BUFB  (3*PLB)           // A, Wh, Wl = 30720 bytes per buffer
#define TG_SMEM (2*BUFB)        // 61440

#define MMA16816(acc, a, b) \
    asm volatile("mma.sync.aligned.m16n8k16.row.col.f32.f16.f16.f32 " \
        "{%0,%1,%2,%3},{%4,%5,%6,%7},{%8,%9},{%0,%1,%2,%3};" \
        : "+f"((acc)[0]), "+f"((acc)[1]), "+f"((acc)[2]), "+f"((acc)[3]) \
        : "r"((a)[0]), "r"((a)[1]), "r"((a)[2]), "r"((a)[3]), \
          "r"((b)[0]), "r"((b)[1]))

#define LDSM4(r, addr) \
    asm volatile("ldmatrix.sync.aligned.m8n8.x4.shared.b16 {%0,%1,%2,%3}, [%4];" \
        : "=r"((r)[0]), "=r"((r)[1]), "=r"((r)[2]), "=r"((r)[3]) : "r"(addr))

__device__ __forceinline__ void cpa16(uint32_t s, const void* g, int szr) {
    asm volatile("cp.async.cg.shared.global [%0], [%1], 16, %2;"
                 :: "r"(s), "l"(__cvta_generic_to_global(g)), "r"(szr) : "memory");
}

__global__ __launch_bounds__(256, 2)
void tgemm_k(const __half* __restrict__ A16,
             const __half* __restrict__ Wh, const __half* __restrict__ Wl,
             const float* __restrict__ bias, float* __restrict__ C,
             int N, int K) {
    extern __shared__ __align__(16) char smraw[];
    const uint32_t sb = smem_u32(smraw);
    const int tid  = threadIdx.x;
    const int lane = tid & 31, warp = tid >> 5;
    const int wr = warp >> 2, wc = warp & 3;
    const int gid = lane >> 2, tq = lane & 3;
    const int row0 = blockIdx.y * 128, n0 = blockIdx.x * 128;

    const int rw = lane & 7;
    const uint32_t aoff = (uint32_t)(((rw + ((lane >> 3) & 1) * 8) * SAS + (lane >> 4) * 8) * 2);
    const uint32_t boff = (uint32_t)(((rw + (lane >> 4) * 8) * SAS + ((lane >> 3) & 1) * 8) * 2);

    float acc[4][4][4];
    #pragma unroll
    for (int mi = 0; mi < 4; mi++)
        #pragma unroll
        for (int ni = 0; ni < 4; ni++)
            #pragma unroll
            for (int e = 0; e < 4; e++) acc[mi][ni][e] = 0.f;

    const int nst = (K + 31) >> 5;

    auto issue = [&](int s, int buf) {
        const int k0 = s * 32;
        const uint32_t base = sb + buf * BUFB;
        #pragma unroll
        for (int i = 0; i < 6; i++) {
            int task = i * 256 + tid;          // 0..1535
            int plane = task >> 9;             // 0:A 1:Wh 2:Wl
            int idx = task & 511;
            int r = idx >> 2, c16 = idx & 3;
            uint32_t dst = base + plane * PLB + (uint32_t)((r * SAS + c16 * 8) * 2);
            int k = k0 + c16 * 8;
            const __half* g;
            int sz = 16;
            if (plane == 0) {
                g = A16 + (size_t)(row0 + r) * K + k;
                if (k + 8 > K) sz = 0;
            } else {
                int n = n0 + r;
                g = (plane == 2 ? Wl : Wh) + (size_t)n * K + k;
                if (k + 8 > K || n >= N) sz = 0;
            }
            if (sz == 0) g = A16;
            cpa16(dst, g, sz);
        }
        asm volatile("cp.async.commit_group;" ::: "memory");
    };

    auto compute = [&](int buf) {
        const uint32_t sA = sb + buf * BUFB;
        const uint32_t sW = sA + PLB;
        #pragma unroll
        for (int kk = 0; kk < 32; kk += 16) {
            uint32_t ah[4][4];
            #pragma unroll
            for (int mi = 0; mi < 4; mi++) {
                uint32_t ab = sA + (uint32_t)(((wr * 64 + mi * 16) * SAS + kk) * 2);
                LDSM4(ah[mi], ab + aoff);
            }
            #pragma unroll
            for (int pr = 0; pr < 2; pr++) {
                uint32_t bh2[4], bl2[4];
                uint32_t bb = sW + (uint32_t)(((wc * 32 + pr * 16) * SAS + kk) * 2);
                LDSM4(bh2, bb + boff);
                LDSM4(bl2, bb + PLB + boff);
                #pragma unroll
                for (int q = 0; q < 2; q++) {
                    int ni = pr * 2 + q;
                    #pragma unroll
                    for (int mi = 0; mi < 4; mi++) {
                        MMA16816(acc[mi][ni], ah[mi], &bh2[q * 2]);
                        MMA16816(acc[mi][ni], ah[mi], &bl2[q * 2]);
                    }
                }
            }
        }
    };

    issue(0, 0);
    for (int s = 0; s < nst; s++) {
        if (s + 1 < nst) {
            issue(s + 1, (s + 1) & 1);
            asm volatile("cp.async.wait_group 1;" ::: "memory");
        } else {
            asm volatile("cp.async.wait_group 0;" ::: "memory");
        }
        __syncthreads();
        compute(s & 1);
        __syncthreads();
    }

    #pragma unroll
    for (int mi = 0; mi < 4; mi++) {
        int row = row0 + wr * 64 + mi * 16 + gid;
        #pragma unroll
        for (int ni = 0; ni < 4; ni++) {
            int col = n0 + wc * 32 + ni * 8 + tq * 2;
            if (col < N) {
                float b0 = bias ? bias[col]     : 0.f;
                float b1 = bias ? bias[col + 1] : 0.f;
                float* c0 = C + (size_t)row * N + col;
                c0[0] = acc[mi][ni][0] + b0;
                c0[1] = acc[mi][ni][1] + b1;
                float* c1 = C + (size_t)(row + 8) * N + col;
                c1[0] = acc[mi][ni][2] + b0;
                c1[1] = acc[mi][ni][3] + b1;
            }
        }
    }
}

// ---------------- weight convert+transpose: src[R,C] fp32 -> dst[C,R] hi/lo -
__global__ void convert_wt_k(const float* __restrict__ src,
                             __half* __restrict__ dhi, __half* __restrict__ dlo,
                             int R, int C) {
    __shared__ float tile[32][33];
    int c0 = blockIdx.x * 32, r0 = blockIdx.y * 32;
    int x = c0 + threadIdx.x;
    #pragma unroll
    for (int j = threadIdx.y; j < 32; j += 8) {
        int r = r0 + j;
        tile[j][threadIdx.x] = (r < R && x < C) ? src[(size_t)r * C + x] : 0.f;
    }
    __syncthreads();
    int xr = r0 + threadIdx.x;
    #pragma unroll
    for (int j = threadIdx.y; j < 32; j += 8) {
        int c = c0 + j;
        if (c < C && xr < R) {
            float v = tile[threadIdx.x][j];
            __half h = __float2half_rn(v);
            __half l = __float2half_rn(v - __half2float(h));
            dhi[(size_t)c * R + xr] = h;
            dlo[(size_t)c * R + xr] = l;
        }
    }
}

// ---------------- activation convert: fp32 -> fp16 --------------------------
__global__ void convert_a_k(const float* __restrict__ src,
                            __half* __restrict__ dst, int n) {
    int i = blockIdx.x * 256 + threadIdx.x;
    if (i < n) dst[i] = __float2half_rn(src[i]);
}

// ---------------- mask dtype detector -----------
__global__ void detect_mask_k(const unsigned int* __restrict__ m) {
    __shared__ int s_ni, s_nf;
    if (threadIdx.x == 0) { s_ni = 0; s_nf = 0; }
    __syncthreads();
    int ni = 0, nf = 0;
    for (int i = threadIdx.x; i < 1024; i += blockDim.x) {
        unsigned w = m[i];
        if (w != 0u && w != 1u)           ni = 1;
        if (w != 0u && w != 0x3F800000u)  nf = 1;
    }
    if (ni) atomicOr(&s_ni, 1);
    if (nf) atomicOr(&s_nf, 1);
    __syncthreads();
    if (threadIdx.x == 0)
        g_mask_kind = (!s_ni) ? 0 : ((!s_nf) ? 1 : 2);
}

__global__ void mask_apply_k(const void* __restrict__ maskp,
                             const float* __restrict__ mask_token) {
    int bt = blockIdx.x;
    int kind = g_mask_kind;
    bool is;
    if (kind == 0)      is = ((const int*)maskp)[bt] != 0;
    else if (kind == 1) is = ((const float*)maskp)[bt] != 0.f;
    else                is = ((const unsigned char*)maskp)[bt] != 0;
    if (is) g_h[bt * DM + threadIdx.x] = mask_token[threadIdx.x];
}

// ---------------- LayerNorm(768) with optional fused residual add -----------
__global__ void layernorm_k(float* __restrict__ hbuf,
                            const float* __restrict__ o0, const float* __restrict__ o1,
                            const float* __restrict__ w, const float* __restrict__ b,
                            float* __restrict__ out, __half* __restrict__ out16,
                            int wb) {
    __shared__ float sh[32];
    int row = blockIdx.x;
    float* x = hbuf + (size_t)row * DM;
    int t = threadIdx.x;
    float v0 = x[t], v1 = x[t + 256], v2 = x[t + 512];
    if (o0) {
        const float* a = o0 + (size_t)row * DM;
        const float* c = o1 + (size_t)row * DM;
        v0 += a[t]       + c[t];
        v1 += a[t + 256] + c[t + 256];
        v2 += a[t + 512] + c[t + 512];
        if (wb) { x[t] = v0; x[t + 256] = v1; x[t + 512] = v2; }
    }
    float S  = block_sum(v0 + v1 + v2, sh);
    float mu = S * (1.f / DM);
    float d0 = v0 - mu, d1 = v1 - mu, d2 = v2 - mu;
    float S2 = block_sum(d0 * d0 + d1 * d1 + d2 * d2, sh);
    float inv = rsqrt_acc(S2 * (1.f / DM) + LEPS);
    float r0 = d0 * inv * w[t]       + b[t];
    float r1 = d1 * inv * w[t + 256] + b[t + 256];
    float r2 = d2 * inv * w[t + 512] + b[t + 512];
    if (out) {
        float* o = out + (size_t)row * DM;
        o[t] = r0; o[t + 256] = r1; o[t + 512] = r2;
    }
    if (out16) {
        __half* o = out16 + (size_t)row * DM;
        o[t]       = __float2half_rn(r0);
        o[t + 256] = __float2half_rn(r1);
        o[t + 512] = __float2half_rn(r2);
    }
}

// ---------------- fused conv7+silu and dt/dA (combined grid, per-element) ----
// blocks [0, NCONV): conv elements; blocks [NCONV, NCONV+NDT): dt elements.
__global__ void convdt_k(const float* __restrict__ cw, const float* __restrict__ cb,
                         const float* __restrict__ dt_bias, const float* __restrict__ A_log,
                         int l, int d) {
    const float* __restrict__ src = g_zx[d];
    if (blockIdx.x < NCONV) {
        int idx = blockIdx.x * 256 + threadIdx.x;
        if (idx >= BT * CD) return;
        int c = idx % CD;
        int btt = idx / CD;
        int b = btt >> 10, t = btt & 1023;
        const float* w = cw + ((size_t)(l * 2 + d) * CD + c) * 7;
        float acc = cb[(l * 2 + d) * CD + c];
        if (d == 0) {
            #pragma unroll
            for (int k = 0; k < 7; k++) {
                int tt = t - 6 + k;
                if (tt >= 0) acc = fmaf(w[k], src[(size_t)(b * Tt + tt) * DPJ + 1536 + c], acc);
            }
        } else {
            #pragma unroll
            for (int k = 0; k < 7; k++) {
                int tt = t + 6 - k;
                if (tt < Tt) acc = fmaf(w[k], src[(size_t)(b * Tt + tt) * DPJ + 1536 + c], acc);
            }
        }
        g_xbc[d][idx] = silu_f(acc);
    } else {
        int idx = (blockIdx.x - NCONV) * 256 + threadIdx.x;
        int h = idx % NH;
        int bt = idx / NH;
        float raw = src[(size_t)bt * DPJ + 3104 + h] + dt_bias[(l * 2 + d) * NH + h];
        float dt = (raw > 20.f) ? raw : log1pf(expf(raw));
        float a = -expf(A_log[(l * 2 + d) * NH + h]);
        g_dt[d][idx] = dt;
        g_dA[d][idx] = expf(a * dt);
    }
}

// ---------------- chunked scan pass 1: local scans per chunk -----------------
__global__ void scan1_k(const float* __restrict__ Dp, int l, int d) {
    const int blk = blockIdx.x;
    const int bh = blk >> 4, c = blk & (NCH - 1);
    const int b = bh / NH, hh = bh % NH;
    const int p = threadIdx.x;
    const float* __restrict__ xbc = g_xbc[d];
    const float* __restrict__ dtp = g_dt[d];
    const float* __restrict__ dAp = g_dA[d];
    float* __restrict__ yb = g_y[d];
    float* __restrict__ plb = &g_pl[d][bh * Tt];
    const float Dc = Dp[(l * 2 + d) * NH + hh];
    float s[16];
    #pragma unroll
    for (int n = 0; n < 16; n++) s[n] = 0.f;
    float pl = 1.f;
    for (int il = 0; il < CLEN; il++) {
        int i = c * CLEN + il;
        int t = d ? (Tt - 1 - i) : i;
        int bt = b * Tt + t;
        const float* row = xbc + (size_t)bt * CD;
        float xv = row[hh * HD + p];
        float dt = dtp[bt * NH + hh];
        float dA = dAp[bt * NH + hh];
        float Bv[16], Cv[16];
        #pragma unroll
        for (int q = 0; q < 4; q++) {
            *(float4*)&Bv[q * 4] = *(const float4*)(row + 1536 + q * 4);
            *(float4*)&Cv[q * 4] = *(const float4*)(row + 1552 + q * 4);
        }
        float c0 = dt * xv;
        float a0 = 0.f, a1 = 0.f, a2 = 0.f, a3 = 0.f;
        #pragma unroll
        for (int n = 0; n < 16; n += 4) {
            s[n+0] = fmaf(s[n+0], dA, c0 * Bv[n+0]); a0 = fmaf(s[n+0], Cv[n+0], a0);
            s[n+1] = fmaf(s[n+1], dA, c0 * Bv[n+1]); a1 = fmaf(s[n+1], Cv[n+1], a1);
            s[n+2] = fmaf(s[n+2], dA, c0 * Bv[n+2]); a2 = fmaf(s[n+2], Cv[n+2], a2);
            s[n+3] = fmaf(s[n+3], dA, c0 * Bv[n+3]); a3 = fmaf(s[n+3], Cv[n+3], a3);
        }
        yb[(size_t)bt * DI + hh * HD + p] = (a0 + a1) + (a2 + a3) + Dc * xv;
        pl *= dA;
        if (p == 0) plb[i] = pl;
    }
    float* dst = &g_sloc[d][(size_t)((bh * NCH + c) * HD + p) * DS];
    #pragma unroll
    for (int q = 0; q < 4; q++)
        *(float4*)(dst + q * 4) = make_float4(s[q*4], s[q*4+1], s[q*4+2], s[q*4+3]);
}

// ---------------- chunked scan pass 2: combine chunk states ------------------
__global__ void scan2_k(int d) {
    const int bh = blockIdx.x;
    const int tid = threadIdx.x;
    const int p = tid >> 4, n = tid & 15;
    const float* __restrict__ plb = &g_pl[d][bh * Tt];
    float S = 0.f;
    #pragma unroll
    for (int c = 0; c < NCH; c++) {
        size_t base = (size_t)((bh * NCH + c) * HD + p) * DS + n;
        g_s0[d][base] = S;
        float P  = plb[c * CLEN + CLEN - 1];
        float sl = g_sloc[d][base];
        S = S * P + sl;
    }
}

// ---------------- chunked scan pass 3: apply cross-chunk correction ----------
__global__ void scan3_k(int d) {
    const int blk = blockIdx.x;
    const int bh = blk >> 4, c = blk & (NCH - 1);
    if (c == 0) return;
    const int b = bh / NH, hh = bh % NH;
    const int p = threadIdx.x;
    const float* __restrict__ xbc = g_xbc[d];
    const float* __restrict__ plb = &g_pl[d][bh * Tt];
    float* __restrict__ yb = g_y[d];
    float S[16];
    const float* sp = &g_s0[d][(size_t)((bh * NCH + c) * HD + p) * DS];
    #pragma unroll
    for (int q = 0; q < 4; q++) {
        float4 v = *(const float4*)(sp + q * 4);
        S[q*4] = v.x; S[q*4+1] = v.y; S[q*4+2] = v.z; S[q*4+3] = v.w;
    }
    for (int il = 0; il < CLEN; il++) {
        int i = c * CLEN + il;
        int t = d ? (Tt - 1 - i) : i;
        int bt = b * Tt + t;
        const float* row = xbc + (size_t)bt * CD;
        float Cv[16];
        #pragma unroll
        for (int q = 0; q < 4; q++)
            *(float4*)&Cv[q * 4] = *(const float4*)(row + 1552 + q * 4);
        float pl = plb[i];
        float d0 = 0.f, d1 = 0.f;
        #pragma unroll
        for (int n = 0; n < 16; n += 2) {
            d0 = fmaf(Cv[n], S[n], d0);
            d1 = fmaf(Cv[n+1], S[n+1], d1);
        }
        yb[(size_t)bt * DI + hh * HD + p] += pl * (d0 + d1);
    }
}

// ---------------- gated RMS norm over 1536 -> fp16 plane (per direction) ----
__global__ void gated_rms_k(const float* __restrict__ ssm_w, int l, int d) {
    __shared__ float sh[32];
    int row = blockIdx.x;
    const float* y = g_y[d] + (size_t)row * DI;
    const float* z = g_zx[d] + (size_t)row * DPJ;
    __half* out = g_yn16[d] + (size_t)row * DI;
    const float* w = ssm_w + (l * 2 + d) * DI;
    int t = threadIdx.x;
    float g[6], s2 = 0.f;
    #pragma unroll
    for (int i = 0; i < 6; i++) {
        int c = t + 256 * i;
        float gv = y[c] * silu_f(z[c]);
        g[i] = gv;
        s2 += gv * gv;
    }
    float S2 = block_sum(s2, sh);
    float inv = rsqrt_acc(S2 * (1.f / DI) + LEPS);
    #pragma unroll
    for (int i = 0; i < 6; i++) {
        int c = t + 256 * i;
        out[c] = __float2half_rn(g[i] * inv * w[c]);
    }
}

// ---------------- stream context (3 streams) --------------------------------
struct StreamCtx {
    cudaStream_t s0, s1, s2;
    cudaEvent_t evF, evP, evPO;
    cudaEvent_t evCI[4], evCO[4];
    cudaEvent_t evL[2], evI0[2], evI1[2], evA[2], evB[2];
    int ok;
};
static StreamCtx g_sc = {};

static void sc_init() {
    if (g_sc.ok) return;
    cudaStreamCreateWithFlags(&g_sc.s0, cudaStreamNonBlocking);
    cudaStreamCreateWithFlags(&g_sc.s1, cudaStreamNonBlocking);
    cudaStreamCreateWithFlags(&g_sc.s2, cudaStreamNonBlocking);
    cudaEventCreateWithFlags(&g_sc.evF,  cudaEventDisableTiming);
    cudaEventCreateWithFlags(&g_sc.evP,  cudaEventDisableTiming);
    cudaEventCreateWithFlags(&g_sc.evPO, cudaEventDisableTiming);
    for (int i = 0; i < 4; i++) {
        cudaEventCreateWithFlags(&g_sc.evCI[i], cudaEventDisableTiming);
        cudaEventCreateWithFlags(&g_sc.evCO[i], cudaEventDisableTiming);
    }
    for (int i = 0; i < 2; i++) {
        cudaEventCreateWithFlags(&g_sc.evL[i],  cudaEventDisableTiming);
        cudaEventCreateWithFlags(&g_sc.evI0[i], cudaEventDisableTiming);
        cudaEventCreateWithFlags(&g_sc.evI1[i], cudaEventDisableTiming);
        cudaEventCreateWithFlags(&g_sc.evA[i],  cudaEventDisableTiming);
        cudaEventCreateWithFlags(&g_sc.evB[i],  cudaEventDisableTiming);
    }
    g_sc.ok = 1;
}

// ---------------- launcher ---------------------------------------------------
extern "C" void kernel_launch(void* const* d_in, const int* in_sizes, int n_in,
                              void* d_out, int out_size) {
    const float* x          = (const float*)d_in[0];
    const void*  maskp      = d_in[1];
    const float* proj_in_w  = (const float*)d_in[2];
    const float* proj_in_b  = (const float*)d_in[3];
    const float* mask_token = (const float*)d_in[4];
    const float* ln_w       = (const float*)d_in[5];
    const float* ln_b       = (const float*)d_in[6];
    const float* in_proj_w  = (const float*)d_in[7];
    const float* in_proj_b  = (const float*)d_in[8];
    const float* conv_w     = (const float*)d_in[9];
    const float* conv_b     = (const float*)d_in[10];
    const float* dt_bias    = (const float*)d_in[11];
    const float* A_log      = (const float*)d_in[12];
    const float* Dp         = (const float*)d_in[13];
    const float* ssm_w      = (const float*)d_in[14];
    const float* out_proj_w = (const float*)d_in[15];
    const float* fn_w       = (const float*)d_in[16];
    const float* fn_b       = (const float*)d_in[17];
    const float* proj_out_w = (const float*)d_in[18];
    const float* proj_out_b = (const float*)d_in[19];
    float* out = (float*)d_out;

    sc_init();
    cudaStream_t S0 = g_sc.s0, S1 = g_sc.s1, S2 = g_sc.s2;
    cudaStream_t STD = (cudaStream_t)0;

    float *p_h, *p_hn, *p_zx, *p_o;
    __half *p_wih, *p_wil, *p_woh, *p_wol, *p_wpih, *p_wpil, *p_wpoh, *p_wpol;
    __half *p_hn16, *p_yn16, *p_x16;
    cudaGetSymbolAddress((void**)&p_h,    g_h);
    cudaGetSymbolAddress((void**)&p_hn,   g_hn);
    cudaGetSymbolAddress((void**)&p_zx,   g_zx);
    cudaGetSymbolAddress((void**)&p_o,    g_o);
    cudaGetSymbolAddress((void**)&p_wih,  g_wih);
    cudaGetSymbolAddress((void**)&p_wil,  g_wil);
    cudaGetSymbolAddress((void**)&p_woh,  g_woh);
    cudaGetSymbolAddress((void**)&p_wol,  g_wol);
    cudaGetSymbolAddress((void**)&p_wpih, g_wpih);
    cudaGetSymbolAddress((void**)&p_wpil, g_wpil);
    cudaGetSymbolAddress((void**)&p_wpoh, g_wpoh);
    cudaGetSymbolAddress((void**)&p_wpol, g_wpol);
    cudaGetSymbolAddress((void**)&p_hn16, g_hn16);
    cudaGetSymbolAddress((void**)&p_yn16, g_yn16);
    cudaGetSymbolAddress((void**)&p_x16,  g_x16);

    cudaFuncSetAttribute(tgemm_k, cudaFuncAttributeMaxDynamicSharedMemorySize, TG_SMEM);

    dim3 tb(32, 8);

    // ---- fork from capture stream
    detect_mask_k<<<1, 256, 0, STD>>>((const unsigned int*)maskp);
    cudaEventRecord(g_sc.evF, STD);
    cudaStreamWaitEvent(S0, g_sc.evF, 0);
    cudaStreamWaitEvent(S1, g_sc.evF, 0);
    cudaStreamWaitEvent(S2, g_sc.evF, 0);

    // ---- S2: weight conversions (layer-0 in_proj first)
    for (int i = 0; i < 2; i++) {
        convert_wt_k<<<dim3((DPJ + 31) / 32, (DM + 31) / 32), tb, 0, S2>>>(
            in_proj_w + (size_t)i * DM * DPJ,
            p_wih + (size_t)i * DPJ * DM, p_wil + (size_t)i * DPJ * DM, DM, DPJ);
        cudaEventRecord(g_sc.evCI[i], S2);
    }
    for (int i = 0; i < 2; i++) {
        convert_wt_k<<<dim3((DM + 31) / 32, (DI + 31) / 32), tb, 0, S2>>>(
            out_proj_w + (size_t)i * DI * DM,
            p_woh + (size_t)i * DM * DI, p_wol + (size_t)i * DM * DI, DI, DM);
        cudaEventRecord(g_sc.evCO[i], S2);
    }
    for (int i = 2; i < 4; i++) {
        convert_wt_k<<<dim3((DPJ + 31) / 32, (DM + 31) / 32), tb, 0, S2>>>(
            in_proj_w + (size_t)i * DM * DPJ,
            p_wih + (size_t)i * DPJ * DM, p_wil + (size_t)i * DPJ * DM, DM, DPJ);
        cudaEventRecord(g_sc.evCI[i], S2);
    }
    for (int i = 2; i < 4; i++) {
        convert_wt_k<<<dim3((DM + 31) / 32, (DI + 31) / 32), tb, 0, S2>>>(
            out_proj_w + (size_t)i * DI * DM,
            p_woh + (size_t)i * DM * DI, p_wol + (size_t)i * DM * DI, DI, DM);
        cudaEventRecord(g_sc.evCO[i], S2);
    }
    convert_wt_k<<<dim3((DIN + 31) / 32, (DM + 31) / 32), tb, 0, S2>>>(
        proj_out_w, p_wpoh, p_wpol, DM, DIN);
    cudaEventRecord(g_sc.evPO, S2);

    // ---- S0: proj_in path
    convert_wt_k<<<dim3((DM + 31) / 32, (DIN + 31) / 32), tb, 0, S0>>>(proj_in_w, p_wpih, p_wpil, DIN, DM);
    convert_a_k<<<(BT * DIN + 255) / 256, 256, 0, S0>>>(x, p_x16, BT * DIN);
    tgemm_k<<<dim3(DM / 128, BT / 128), 256, TG_SMEM, S0>>>(
        p_x16, p_wpih, p_wpil, proj_in_b, p_h, DM, DIN);
    mask_apply_k<<<BT, DM, 0, S0>>>(maskp, mask_token);
    cudaEventRecord(g_sc.evP, S0);

    cudaStreamWaitEvent(STD, g_sc.evP, 0);

    for (int l = 0; l < 2; l++) {
        layernorm_k<<<BT, 256, 0, STD>>>(
            p_h,
            l ? p_o : nullptr, l ? p_o + (size_t)BT * DM : nullptr,
            ln_w + l * DM, ln_b + l * DM, nullptr, p_hn16, 1);
        cudaEventRecord(g_sc.evL[l], STD);

        // ---- d0 on S0 (no skew — both in_projs run concurrently)
        cudaStreamWaitEvent(S0, g_sc.evL[l], 0);
        cudaStreamWaitEvent(S0, g_sc.evCI[l * 2 + 0], 0);
        tgemm_k<<<dim3((DPJ + 127) / 128, BT / 128), 256, TG_SMEM, S0>>>(
            p_hn16,
            p_wih + (size_t)(l * 2 + 0) * DPJ * DM,
            p_wil + (size_t)(l * 2 + 0) * DPJ * DM,
            in_proj_b + (size_t)(l * 2 + 0) * DPJ,
            p_zx, DPJ, DM);
        convdt_k<<<NCONV + NDT, 256, 0, S0>>>(conv_w, conv_b, dt_bias, A_log, l, 0);
        scan1_k<<<96 * NCH, HD, 0, S0>>>(Dp, l, 0);
        scan2_k<<<96, HD * DS, 0, S0>>>(0);
        scan3_k<<<96 * NCH, HD, 0, S0>>>(0);
        gated_rms_k<<<BT, 256, 0, S0>>>(ssm_w, l, 0);

        // ---- d1 on S1 (concurrent with d0)
        cudaStreamWaitEvent(S1, g_sc.evL[l], 0);
        cudaStreamWaitEvent(S1, g_sc.evCI[l * 2 + 1], 0);
        tgemm_k<<<dim3((DPJ + 127) / 128, BT / 128), 256, TG_SMEM, S1>>>(
            p_hn16,
            p_wih + (size_t)(l * 2 + 1) * DPJ * DM,
            p_wil + (size_t)(l * 2 + 1) * DPJ * DM,
            in_proj_b + (size_t)(l * 2 + 1) * DPJ,
            p_zx + (size_t)BT * DPJ, DPJ, DM);
        convdt_k<<<NCONV + NDT, 256, 0, S1>>>(conv_w, conv_b, dt_bias, A_log, l, 1);
        scan1_k<<<96 * NCH, HD, 0, S1>>>(Dp, l, 1);
        scan2_k<<<96, HD * DS, 0, S1>>>(1);
        scan3_k<<<96 * NCH, HD, 0, S1>>>(1);
        gated_rms_k<<<BT, 256, 0, S1>>>(ssm_w, l, 1);

        // ---- out_proj d0 (after its own chain only)
        cudaStreamWaitEvent(S0, g_sc.evCO[l * 2 + 0], 0);
        tgemm_k<<<dim3(DM / 128, BT / 128), 256, TG_SMEM, S0>>>(
            p_yn16,
            p_woh + (size_t)(l * 2 + 0) * DM * DI,
            p_wol + (size_t)(l * 2 + 0) * DM * DI,
            nullptr, p_o, DM, DI);
        cudaEventRecord(g_sc.evA[l], S0);

        // ---- out_proj d1
        cudaStreamWaitEvent(S1, g_sc.evCO[l * 2 + 1], 0);
        tgemm_k<<<dim3(DM / 128, BT / 128), 256, TG_SMEM, S1>>>(
            p_yn16 + (size_t)BT * DI,
            p_woh + (size_t)(l * 2 + 1) * DM * DI,
            p_wol + (size_t)(l * 2 + 1) * DM * DI,
            nullptr, p_o + (size_t)BT * DM, DM, DI);
        cudaEventRecord(g_sc.evB[l], S1);

        cudaStreamWaitEvent(STD, g_sc.evA[l], 0);
        cudaStreamWaitEvent(STD, g_sc.evB[l], 0);
    }

    // outputs: hidden = LN(h + o0 + o1, final); pred = hidden16 @ proj_out + b
    const int PRED = BT * DIN, HID = BT * DM;
    float* predp = nullptr;
    float* hidp  = nullptr;
    if (out_size >= PRED + HID)      { predp = out; hidp = out + PRED; }
    else if (out_size == PRED)       { predp = out; }
    else                             { hidp = out; }

    layernorm_k<<<BT, 256, 0, STD>>>(
        p_h, p_o, p_o + (size_t)BT * DM,
        fn_w, fn_b, hidp ? hidp : p_hn, p_hn16, 0);
    if (predp) {
        cudaStreamWaitEvent(STD, g_sc.evPO, 0);
        tgemm_k<<<dim3((DIN + 127) / 128, BT / 128), 256, TG_SMEM, STD>>>(
            p_hn16, p_wpoh, p_wpol, proj_out_b, predp, DIN, DM);
    }
}

// round 17
// speedup vs baseline: 1.1132x; 1.0544x over previous
#include <cuda_runtime.h>
#include <cuda_fp16.h>
#include <math.h>
#include <stdint.h>

#define Bb   4
#define Tt   1024
#define BT   4096          // Bb*Tt tokens
#define DM   768
#define DI   1536
#define NH   24
#define HD   64
#define DS   16
#define CD   1568          // D_INNER + 2*D_STATE
#define DPJ  3128          // 2*DI + 2*DS + NH
#define DIN  80
#define NCH  16            // scan chunks
#define CLEN 64            // steps per chunk
#define NCONV ((BT*CD + 255) / 256)   // 25088 conv blocks
#define NDT   (BT*NH / 256)           // 384 dt blocks
#define LEPS 1e-5f

// ---------------- scratch (device globals; no allocations allowed) ----------
__device__ float g_h  [BT*DM];
__device__ float g_hn [BT*DM];
__device__ float g_zx [2][BT*DPJ];
__device__ float g_xbc[2][BT*CD];
__device__ float g_dt [2][BT*NH];
__device__ float g_dA [2][BT*NH];
__device__ float g_y  [2][BT*DI];
__device__ float g_o  [2][BT*DM];
__device__ int   g_mask_kind;   // 0=int32, 1=float32, 2=uint8/bool
// chunked-scan scratch
__device__ float g_sloc[2][96*NCH*HD*DS];
__device__ float g_s0  [2][96*NCH*HD*DS];
__device__ float g_pl  [2][96*Tt];
// fp16 weight planes, transposed to [N,K]
__device__ __half g_wih[4][DPJ*DM], g_wil[4][DPJ*DM];
__device__ __half g_woh[4][DM*DI],  g_wol[4][DM*DI];
__device__ __half g_wpih[DM*DIN],   g_wpil[DM*DIN];
__device__ __half g_wpoh[DIN*DM],   g_wpol[DIN*DM];
// fp16 activation planes
__device__ __half g_hn16[BT*DM];
__device__ __half g_yn16[2][BT*DI];
__device__ __half g_x16 [BT*DIN];

// ---------------- generic helpers ----------------
__device__ __forceinline__ float block_sum(float v, float* sh) {
    int lane = threadIdx.x & 31, wid = threadIdx.x >> 5;
    #pragma unroll
    for (int o = 16; o > 0; o >>= 1) v += __shfl_xor_sync(0xffffffffu, v, o);
    if (lane == 0) sh[wid] = v;
    __syncthreads();
    int nw = (blockDim.x + 31) >> 5;
    if (threadIdx.x < 32) {
        float t = (threadIdx.x < nw) ? sh[threadIdx.x] : 0.f;
        #pragma unroll
        for (int o = 16; o > 0; o >>= 1) t += __shfl_xor_sync(0xffffffffu, t, o);
        if (threadIdx.x == 0) sh[0] = t;
    }
    __syncthreads();
    float r = sh[0];
    __syncthreads();
    return r;
}

__device__ __forceinline__ float rsqrt_acc(float a) {
    float r = rsqrtf(a);
    r = r * (1.5f - 0.5f * a * r * r);
    return r;
}

__device__ __forceinline__ float silu_f(float v) {
    return v / (1.f + expf(-v));
}

__device__ __forceinline__ uint32_t smem_u32(const void* p) {
    uint32_t a;
    asm("{ .reg .u64 t; cvta.to.shared.u64 t, %1; cvt.u32.u64 %0, t; }" : "=r"(a) : "l"(p));
    return a;
}

// ---------------- tensor-core GEMM (fp16 x2), 3-stage single-sync pipeline --
#define SAS   40                // half row stride in smem (80 bytes)
#define PLB   10240             // bytes per plane: 128*40*2
#define BUFB  (3*PLB)           // A, Wh, Wl = 30720 bytes per buffer
#define TG_SMEM (3*BUFB)        // 92160 (3 stages)

#define MMA16816(acc, a, b) \
    asm volatile("mma.sync.aligned.m16n8k16.row.col.f32.f16.f16.f32 " \
        "{%0,%1,%2,%3},{%4,%5,%6,%7},{%8,%9},{%0,%1,%2,%3};" \
        : "+f"((acc)[0]), "+f"((acc)[1]), "+f"((acc)[2]), "+f"((acc)[3]) \
        : "r"((a)[0]), "r"((a)[1]), "r"((a)[2]), "r"((a)[3]), \
          "r"((b)[0]), "r"((b)[1]))

#define LDSM4(r, addr) \
    asm volatile("ldmatrix.sync.aligned.m8n8.x4.shared.b16 {%0,%1,%2,%3}, [%4];" \
        : "=r"((r)[0]), "=r"((r)[1]), "=r"((r)[2]), "=r"((r)[3]) : "r"(addr))

__device__ __forceinline__ void cpa16(uint32_t s, const void* g, int szr) {
    asm volatile("cp.async.cg.shared.global [%0], [%1], 16, %2;"
                 :: "r"(s), "l"(__cvta_generic_to_global(g)), "r"(szr) : "memory");
}

__global__ __launch_bounds__(256, 2)
void tgemm_k(const __half* __restrict__ A16,
             const __half* __restrict__ Wh, const __half* __restrict__ Wl,
             const float* __restrict__ bias, float* __restrict__ C,
             int N, int K) {
    extern __shared__ __align__(16) char smraw[];
    const uint32_t sb = smem_u32(smraw);
    const int tid  = threadIdx.x;
    const int lane = tid & 31, warp = tid >> 5;
    const int wr = warp >> 2, wc = warp & 3;
    const int gid = lane >> 2, tq = lane & 3;
    const int row0 = blockIdx.y * 128, n0 = blockIdx.x * 128;

    const int rw = lane & 7;
    const uint32_t aoff = (uint32_t)(((rw + ((lane >> 3) & 1) * 8) * SAS + (lane >> 4) * 8) * 2);
    const uint32_t boff = (uint32_t)(((rw + (lane >> 4) * 8) * SAS + ((lane >> 3) & 1) * 8) * 2);

    float acc[4][4][4];
    #pragma unroll
    for (int mi = 0; mi < 4; mi++)
        #pragma unroll
        for (int ni = 0; ni < 4; ni++)
            #pragma unroll
            for (int e = 0; e < 4; e++) acc[mi][ni][e] = 0.f;

    const int nst = (K + 31) >> 5;

    auto issue = [&](int s, int buf) {
        const int k0 = s * 32;
        const uint32_t base = sb + buf * BUFB;
        #pragma unroll
        for (int i = 0; i < 6; i++) {
            int task = i * 256 + tid;          // 0..1535
            int plane = task >> 9;             // 0:A 1:Wh 2:Wl
            int idx = task & 511;
            int r = idx >> 2, c16 = idx & 3;
            uint32_t dst = base + plane * PLB + (uint32_t)((r * SAS + c16 * 8) * 2);
            int k = k0 + c16 * 8;
            const __half* g;
            int sz = 16;
            if (plane == 0) {
                g = A16 + (size_t)(row0 + r) * K + k;
                if (k + 8 > K) sz = 0;
            } else {
                int n = n0 + r;
                g = (plane == 2 ? Wl : Wh) + (size_t)n * K + k;
                if (k + 8 > K || n >= N) sz = 0;
            }
            if (sz == 0) g = A16;
            cpa16(dst, g, sz);
        }
        asm volatile("cp.async.commit_group;" ::: "memory");
    };

    auto compute = [&](int buf) {
        const uint32_t sA = sb + buf * BUFB;
        const uint32_t sW = sA + PLB;
        #pragma unroll
        for (int kk = 0; kk < 32; kk += 16) {
            uint32_t ah[4][4];
            #pragma unroll
            for (int mi = 0; mi < 4; mi++) {
                uint32_t ab = sA + (uint32_t)(((wr * 64 + mi * 16) * SAS + kk) * 2);
                LDSM4(ah[mi], ab + aoff);
            }
            #pragma unroll
            for (int pr = 0; pr < 2; pr++) {
                uint32_t bh2[4], bl2[4];
                uint32_t bb = sW + (uint32_t)(((wc * 32 + pr * 16) * SAS + kk) * 2);
                LDSM4(bh2, bb + boff);
                LDSM4(bl2, bb + PLB + boff);
                #pragma unroll
                for (int q = 0; q < 2; q++) {
                    int ni = pr * 2 + q;
                    #pragma unroll
                    for (int mi = 0; mi < 4; mi++) {
                        MMA16816(acc[mi][ni], ah[mi], &bh2[q * 2]);
                        MMA16816(acc[mi][ni], ah[mi], &bl2[q * 2]);
                    }
                }
            }
        }
    };

    // 3-stage pipeline, one barrier per stage.
    // At iter s: wait stage s, bar, compute buf s%3, then issue s+2 into
    // buf (s+2)%3 (last read by compute(s-1), which the barrier at iter s
    // already ordered across all warps).
    issue(0, 0);
    if (nst > 1) issue(1, 1);
    for (int s = 0; s < nst; s++) {
        if (s + 1 < nst) {
            asm volatile("cp.async.wait_group 1;" ::: "memory");
        } else {
            asm volatile("cp.async.wait_group 0;" ::: "memory");
        }
        __syncthreads();
        compute(s % 3);
        if (s + 2 < nst) issue(s + 2, (s + 2) % 3);
    }

    #pragma unroll
    for (int mi = 0; mi < 4; mi++) {
        int row = row0 + wr * 64 + mi * 16 + gid;
        #pragma unroll
        for (int ni = 0; ni < 4; ni++) {
            int col = n0 + wc * 32 + ni * 8 + tq * 2;
            if (col < N) {
                float b0 = bias ? bias[col]     : 0.f;
                float b1 = bias ? bias[col + 1] : 0.f;
                float* c0 = C + (size_t)row * N + col;
                c0[0] = acc[mi][ni][0] + b0;
                c0[1] = acc[mi][ni][1] + b1;
                float* c1 = C + (size_t)(row + 8) * N + col;
                c1[0] = acc[mi][ni][2] + b0;
                c1[1] = acc[mi][ni][3] + b1;
            }
        }
    }
}

// ---------------- weight convert+transpose: src[R,C] fp32 -> dst[C,R] hi/lo -
__global__ void convert_wt_k(const float* __restrict__ src,
                             __half* __restrict__ dhi, __half* __restrict__ dlo,
                             int R, int C) {
    __shared__ float tile[32][33];
    int c0 = blockIdx.x * 32, r0 = blockIdx.y * 32;
    int x = c0 + threadIdx.x;
    #pragma unroll
    for (int j = threadIdx.y; j < 32; j += 8) {
        int r = r0 + j;
        tile[j][threadIdx.x] = (r < R && x < C) ? src[(size_t)r * C + x] : 0.f;
    }
    __syncthreads();
    int xr = r0 + threadIdx.x;
    #pragma unroll
    for (int j = threadIdx.y; j < 32; j += 8) {
        int c = c0 + j;
        if (c < C && xr < R) {
            float v = tile[threadIdx.x][j];
            __half h = __float2half_rn(v);
            __half l = __float2half_rn(v - __half2float(h));
            dhi[(size_t)c * R + xr] = h;
            dlo[(size_t)c * R + xr] = l;
        }
    }
}

// ---------------- activation convert: fp32 -> fp16 --------------------------
__global__ void convert_a_k(const float* __restrict__ src,
                            __half* __restrict__ dst, int n) {
    int i = blockIdx.x * 256 + threadIdx.x;
    if (i < n) dst[i] = __float2half_rn(src[i]);
}

// ---------------- mask dtype detector -----------
__global__ void detect_mask_k(const unsigned int* __restrict__ m) {
    __shared__ int s_ni, s_nf;
    if (threadIdx.x == 0) { s_ni = 0; s_nf = 0; }
    __syncthreads();
    int ni = 0, nf = 0;
    for (int i = threadIdx.x; i < 1024; i += blockDim.x) {
        unsigned w = m[i];
        if (w != 0u && w != 1u)           ni = 1;
        if (w != 0u && w != 0x3F800000u)  nf = 1;
    }
    if (ni) atomicOr(&s_ni, 1);
    if (nf) atomicOr(&s_nf, 1);
    __syncthreads();
    if (threadIdx.x == 0)
        g_mask_kind = (!s_ni) ? 0 : ((!s_nf) ? 1 : 2);
}

__global__ void mask_apply_k(const void* __restrict__ maskp,
                             const float* __restrict__ mask_token) {
    int bt = blockIdx.x;
    int kind = g_mask_kind;
    bool is;
    if (kind == 0)      is = ((const int*)maskp)[bt] != 0;
    else if (kind == 1) is = ((const float*)maskp)[bt] != 0.f;
    else                is = ((const unsigned char*)maskp)[bt] != 0;
    if (is) g_h[bt * DM + threadIdx.x] = mask_token[threadIdx.x];
}

// ---------------- LayerNorm(768) with optional fused residual add -----------
__global__ void layernorm_k(float* __restrict__ hbuf,
                            const float* __restrict__ o0, const float* __restrict__ o1,
                            const float* __restrict__ w, const float* __restrict__ b,
                            float* __restrict__ out, __half* __restrict__ out16,
                            int wb) {
    __shared__ float sh[32];
    int row = blockIdx.x;
    float* x = hbuf + (size_t)row * DM;
    int t = threadIdx.x;
    float v0 = x[t], v1 = x[t + 256], v2 = x[t + 512];
    if (o0) {
        const float* a = o0 + (size_t)row * DM;
        const float* c = o1 + (size_t)row * DM;
        v0 += a[t]       + c[t];
        v1 += a[t + 256] + c[t + 256];
        v2 += a[t + 512] + c[t + 512];
        if (wb) { x[t] = v0; x[t + 256] = v1; x[t + 512] = v2; }
    }
    float S  = block_sum(v0 + v1 + v2, sh);
    float mu = S * (1.f / DM);
    float d0 = v0 - mu, d1 = v1 - mu, d2 = v2 - mu;
    float S2 = block_sum(d0 * d0 + d1 * d1 + d2 * d2, sh);
    float inv = rsqrt_acc(S2 * (1.f / DM) + LEPS);
    float r0 = d0 * inv * w[t]       + b[t];
    float r1 = d1 * inv * w[t + 256] + b[t + 256];
    float r2 = d2 * inv * w[t + 512] + b[t + 512];
    if (out) {
        float* o = out + (size_t)row * DM;
        o[t] = r0; o[t + 256] = r1; o[t + 512] = r2;
    }
    if (out16) {
        __half* o = out16 + (size_t)row * DM;
        o[t]       = __float2half_rn(r0);
        o[t + 256] = __float2half_rn(r1);
        o[t + 512] = __float2half_rn(r2);
    }
}

// ---------------- fused conv7+silu and dt/dA (combined grid, per-element) ----
__global__ void convdt_k(const float* __restrict__ cw, const float* __restrict__ cb,
                         const float* __restrict__ dt_bias, const float* __restrict__ A_log,
                         int l, int d) {
    const float* __restrict__ src = g_zx[d];
    if (blockIdx.x < NCONV) {
        int idx = blockIdx.x * 256 + threadIdx.x;
        if (idx >= BT * CD) return;
        int c = idx % CD;
        int btt = idx / CD;
        int b = btt >> 10, t = btt & 1023;
        const float* w = cw + ((size_t)(l * 2 + d) * CD + c) * 7;
        float acc = cb[(l * 2 + d) * CD + c];
        if (d == 0) {
            #pragma unroll
            for (int k = 0; k < 7; k++) {
                int tt = t - 6 + k;
                if (tt >= 0) acc = fmaf(w[k], src[(size_t)(b * Tt + tt) * DPJ + 1536 + c], acc);
            }
        } else {
            #pragma unroll
            for (int k = 0; k < 7; k++) {
                int tt = t + 6 - k;
                if (tt < Tt) acc = fmaf(w[k], src[(size_t)(b * Tt + tt) * DPJ + 1536 + c], acc);
            }
        }
        g_xbc[d][idx] = silu_f(acc);
    } else {
        int idx = (blockIdx.x - NCONV) * 256 + threadIdx.x;
        int h = idx % NH;
        int bt = idx / NH;
        float raw = src[(size_t)bt * DPJ + 3104 + h] + dt_bias[(l * 2 + d) * NH + h];
        float dt = (raw > 20.f) ? raw : log1pf(expf(raw));
        float a = -expf(A_log[(l * 2 + d) * NH + h]);
        g_dt[d][idx] = dt;
        g_dA[d][idx] = expf(a * dt);
    }
}

// ---------------- chunked scan pass 1: local scans per chunk -----------------
__global__ void scan1_k(const float* __restrict__ Dp, int l, int d) {
    const int blk = blockIdx.x;
    const int bh = blk >> 4, c = blk & (NCH - 1);
    const int b = bh / NH, hh = bh % NH;
    const int p = threadIdx.x;
    const float* __restrict__ xbc = g_xbc[d];
    const float* __restrict__ dtp = g_dt[d];
    const float* __restrict__ dAp = g_dA[d];
    float* __restrict__ yb = g_y[d];
    float* __restrict__ plb = &g_pl[d][bh * Tt];
    const float Dc = Dp[(l * 2 + d) * NH + hh];
    float s[16];
    #pragma unroll
    for (int n = 0; n < 16; n++) s[n] = 0.f;
    float pl = 1.f;
    for (int il = 0; il < CLEN; il++) {
        int i = c * CLEN + il;
        int t = d ? (Tt - 1 - i) : i;
        int bt = b * Tt + t;
        const float* row = xbc + (size_t)bt * CD;
        float xv = row[hh * HD + p];
        float dt = dtp[bt * NH + hh];
        float dA = dAp[bt * NH + hh];
        float Bv[16], Cv[16];
        #pragma unroll
        for (int q = 0; q < 4; q++) {
            *(float4*)&Bv[q * 4] = *(const float4*)(row + 1536 + q * 4);
            *(float4*)&Cv[q * 4] = *(const float4*)(row + 1552 + q * 4);
        }
        float c0 = dt * xv;
        float a0 = 0.f, a1 = 0.f, a2 = 0.f, a3 = 0.f;
        #pragma unroll
        for (int n = 0; n < 16; n += 4) {
            s[n+0] = fmaf(s[n+0], dA, c0 * Bv[n+0]); a0 = fmaf(s[n+0], Cv[n+0], a0);
            s[n+1] = fmaf(s[n+1], dA, c0 * Bv[n+1]); a1 = fmaf(s[n+1], Cv[n+1], a1);
            s[n+2] = fmaf(s[n+2], dA, c0 * Bv[n+2]); a2 = fmaf(s[n+2], Cv[n+2], a2);
            s[n+3] = fmaf(s[n+3], dA, c0 * Bv[n+3]); a3 = fmaf(s[n+3], Cv[n+3], a3);
        }
        yb[(size_t)bt * DI + hh * HD + p] = (a0 + a1) + (a2 + a3) + Dc * xv;
        pl *= dA;
        if (p == 0) plb[i] = pl;
    }
    float* dst = &g_sloc[d][(size_t)((bh * NCH + c) * HD + p) * DS];
    #pragma unroll
    for (int q = 0; q < 4; q++)
        *(float4*)(dst + q * 4) = make_float4(s[q*4], s[q*4+1], s[q*4+2], s[q*4+3]);
}

// ---------------- chunked scan pass 2: combine chunk states ------------------
__global__ void scan2_k(int d) {
    const int bh = blockIdx.x;
    const int tid = threadIdx.x;
    const int p = tid >> 4, n = tid & 15;
    const float* __restrict__ plb = &g_pl[d][bh * Tt];
    float S = 0.f;
    #pragma unroll
    for (int c = 0; c < NCH; c++) {
        size_t base = (size_t)((bh * NCH + c) * HD + p) * DS + n;
        g_s0[d][base] = S;
        float P  = plb[c * CLEN + CLEN - 1];
        float sl = g_sloc[d][base];
        S = S * P + sl;
    }
}

// ---------------- chunked scan pass 3: apply cross-chunk correction ----------
__global__ void scan3_k(int d) {
    const int blk = blockIdx.x;
    const int bh = blk >> 4, c = blk & (NCH - 1);
    if (c == 0) return;
    const int b = bh / NH, hh = bh % NH;
    const int p = threadIdx.x;
    const float* __restrict__ xbc = g_xbc[d];
    const float* __restrict__ plb = &g_pl[d][bh * Tt];
    float* __restrict__ yb = g_y[d];
    float S[16];
    const float* sp = &g_s0[d][(size_t)((bh * NCH + c) * HD + p) * DS];
    #pragma unroll
    for (int q = 0; q < 4; q++) {
        float4 v = *(const float4*)(sp + q * 4);
        S[q*4] = v.x; S[q*4+1] = v.y; S[q*4+2] = v.z; S[q*4+3] = v.w;
    }
    for (int il = 0; il < CLEN; il++) {
        int i = c * CLEN + il;
        int t = d ? (Tt - 1 - i) : i;
        int bt = b * Tt + t;
        const float* row = xbc + (size_t)bt * CD;
        float Cv[16];
        #pragma unroll
        for (int q = 0; q < 4; q++)
            *(float4*)&Cv[q * 4] = *(const float4*)(row + 1552 + q * 4);
        float pl = plb[i];
        float d0 = 0.f, d1 = 0.f;
        #pragma unroll
        for (int n = 0; n < 16; n += 2) {
            d0 = fmaf(Cv[n], S[n], d0);
            d1 = fmaf(Cv[n+1], S[n+1], d1);
        }
        yb[(size_t)bt * DI + hh * HD + p] += pl * (d0 + d1);
    }
}

// ---------------- gated RMS norm over 1536 -> fp16 plane (per direction) ----
__global__ void gated_rms_k(const float* __restrict__ ssm_w, int l, int d) {
    __shared__ float sh[32];
    int row = blockIdx.x;
    const float* y = g_y[d] + (size_t)row * DI;
    const float* z = g_zx[d] + (size_t)row * DPJ;
    __half* out = g_yn16[d] + (size_t)row * DI;
    const float* w = ssm_w + (l * 2 + d) * DI;
    int t = threadIdx.x;
    float g[6], s2 = 0.f;
    #pragma unroll
    for (int i = 0; i < 6; i++) {
        int c = t + 256 * i;
        float gv = y[c] * silu_f(z[c]);
        g[i] = gv;
        s2 += gv * gv;
    }
    float S2 = block_sum(s2, sh);
    float inv = rsqrt_acc(S2 * (1.f / DI) + LEPS);
    #pragma unroll
    for (int i = 0; i < 6; i++) {
        int c = t + 256 * i;
        out[c] = __float2half_rn(g[i] * inv * w[c]);
    }
}

// ---------------- stream context (3 streams) --------------------------------
struct StreamCtx {
    cudaStream_t s0, s1, s2;
    cudaEvent_t evF, evP, evPO;
    cudaEvent_t evCI[4], evCO[4];
    cudaEvent_t evL[2], evI0[2], evI1[2], evA[2], evB[2];
    int ok;
};
static StreamCtx g_sc = {};

static void sc_init() {
    if (g_sc.ok) return;
    cudaStreamCreateWithFlags(&g_sc.s0, cudaStreamNonBlocking);
    cudaStreamCreateWithFlags(&g_sc.s1, cudaStreamNonBlocking);
    cudaStreamCreateWithFlags(&g_sc.s2, cudaStreamNonBlocking);
    cudaEventCreateWithFlags(&g_sc.evF,  cudaEventDisableTiming);
    cudaEventCreateWithFlags(&g_sc.evP,  cudaEventDisableTiming);
    cudaEventCreateWithFlags(&g_sc.evPO, cudaEventDisableTiming);
    for (int i = 0; i < 4; i++) {
        cudaEventCreateWithFlags(&g_sc.evCI[i], cudaEventDisableTiming);
        cudaEventCreateWithFlags(&g_sc.evCO[i], cudaEventDisableTiming);
    }
    for (int i = 0; i < 2; i++) {
        cudaEventCreateWithFlags(&g_sc.evL[i],  cudaEventDisableTiming);
        cudaEventCreateWithFlags(&g_sc.evI0[i], cudaEventDisableTiming);
        cudaEventCreateWithFlags(&g_sc.evI1[i], cudaEventDisableTiming);
        cudaEventCreateWithFlags(&g_sc.evA[i],  cudaEventDisableTiming);
        cudaEventCreateWithFlags(&g_sc.evB[i],  cudaEventDisableTiming);
    }
    g_sc.ok = 1;
}

// ---------------- launcher ---------------------------------------------------
extern "C" void kernel_launch(void* const* d_in, const int* in_sizes, int n_in,
                              void* d_out, int out_size) {
    const float* x          = (const float*)d_in[0];
    const void*  maskp      = d_in[1];
    const float* proj_in_w  = (const float*)d_in[2];
    const float* proj_in_b  = (const float*)d_in[3];
    const float* mask_token = (const float*)d_in[4];
    const float* ln_w       = (const float*)d_in[5];
    const float* ln_b       = (const float*)d_in[6];
    const float* in_proj_w  = (const float*)d_in[7];
    const float* in_proj_b  = (const float*)d_in[8];
    const float* conv_w     = (const float*)d_in[9];
    const float* conv_b     = (const float*)d_in[10];
    const float* dt_bias    = (const float*)d_in[11];
    const float* A_log      = (const float*)d_in[12];
    const float* Dp         = (const float*)d_in[13];
    const float* ssm_w      = (const float*)d_in[14];
    const float* out_proj_w = (const float*)d_in[15];
    const float* fn_w       = (const float*)d_in[16];
    const float* fn_b       = (const float*)d_in[17];
    const float* proj_out_w = (const float*)d_in[18];
    const float* proj_out_b = (const float*)d_in[19];
    float* out = (float*)d_out;

    sc_init();
    cudaStream_t S0 = g_sc.s0, S1 = g_sc.s1, S2 = g_sc.s2;
    cudaStream_t STD = (cudaStream_t)0;

    float *p_h, *p_hn, *p_zx, *p_o;
    __half *p_wih, *p_wil, *p_woh, *p_wol, *p_wpih, *p_wpil, *p_wpoh, *p_wpol;
    __half *p_hn16, *p_yn16, *p_x16;
    cudaGetSymbolAddress((void**)&p_h,    g_h);
    cudaGetSymbolAddress((void**)&p_hn,   g_hn);
    cudaGetSymbolAddress((void**)&p_zx,   g_zx);
    cudaGetSymbolAddress((void**)&p_o,    g_o);
    cudaGetSymbolAddress((void**)&p_wih,  g_wih);
    cudaGetSymbolAddress((void**)&p_wil,  g_wil);
    cudaGetSymbolAddress((void**)&p_woh,  g_woh);
    cudaGetSymbolAddress((void**)&p_wol,  g_wol);
    cudaGetSymbolAddress((void**)&p_wpih, g_wpih);
    cudaGetSymbolAddress((void**)&p_wpil, g_wpil);
    cudaGetSymbolAddress((void**)&p_wpoh, g_wpoh);
    cudaGetSymbolAddress((void**)&p_wpol, g_wpol);
    cudaGetSymbolAddress((void**)&p_hn16, g_hn16);
    cudaGetSymbolAddress((void**)&p_yn16, g_yn16);
    cudaGetSymbolAddress((void**)&p_x16,  g_x16);

    cudaFuncSetAttribute(tgemm_k, cudaFuncAttributeMaxDynamicSharedMemorySize, TG_SMEM);

    dim3 tb(32, 8);

    // ---- fork from capture stream
    detect_mask_k<<<1, 256, 0, STD>>>((const unsigned int*)maskp);
    cudaEventRecord(g_sc.evF, STD);
    cudaStreamWaitEvent(S0, g_sc.evF, 0);
    cudaStreamWaitEvent(S1, g_sc.evF, 0);
    cudaStreamWaitEvent(S2, g_sc.evF, 0);

    // ---- S2: weight conversions (layer-0 in_proj first)
    for (int i = 0; i < 2; i++) {
        convert_wt_k<<<dim3((DPJ + 31) / 32, (DM + 31) / 32), tb, 0, S2>>>(
            in_proj_w + (size_t)i * DM * DPJ,
            p_wih + (size_t)i * DPJ * DM, p_wil + (size_t)i * DPJ * DM, DM, DPJ);
        cudaEventRecord(g_sc.evCI[i], S2);
    }
    for (int i = 0; i < 2; i++) {
        convert_wt_k<<<dim3((DM + 31) / 32, (DI + 31) / 32), tb, 0, S2>>>(
            out_proj_w + (size_t)i * DI * DM,
            p_woh + (size_t)i * DM * DI, p_wol + (size_t)i * DM * DI, DI, DM);
        cudaEventRecord(g_sc.evCO[i], S2);
    }
    for (int i = 2; i < 4; i++) {
        convert_wt_k<<<dim3((DPJ + 31) / 32, (DM + 31) / 32), tb, 0, S2>>>(
            in_proj_w + (size_t)i * DM * DPJ,
            p_wih + (size_t)i * DPJ * DM, p_wil + (size_t)i * DPJ * DM, DM, DPJ);
        cudaEventRecord(g_sc.evCI[i], S2);
    }
    for (int i = 2; i < 4; i++) {
        convert_wt_k<<<dim3((DM + 31) / 32, (DI + 31) / 32), tb, 0, S2>>>(
            out_proj_w + (size_t)i * DI * DM,
            p_woh + (size_t)i * DM * DI, p_wol + (size_t)i * DM * DI, DI, DM);
        cudaEventRecord(g_sc.evCO[i], S2);
    }
    convert_wt_k<<<dim3((DIN + 31) / 32, (DM + 31) / 32), tb, 0, S2>>>(
        proj_out_w, p_wpoh, p_wpol, DM, DIN);
    cudaEventRecord(g_sc.evPO, S2);

    // ---- S0: proj_in path
    convert_wt_k<<<dim3((DM + 31) / 32, (DIN + 31) / 32), tb, 0, S0>>>(proj_in_w, p_wpih, p_wpil, DIN, DM);
    convert_a_k<<<(BT * DIN + 255) / 256, 256, 0, S0>>>(x, p_x16, BT * DIN);
    tgemm_k<<<dim3(DM / 128, BT / 128), 256, TG_SMEM, S0>>>(
        p_x16, p_wpih, p_wpil, proj_in_b, p_h, DM, DIN);
    mask_apply_k<<<BT, DM, 0, S0>>>(maskp, mask_token);
    cudaEventRecord(g_sc.evP, S0);

    cudaStreamWaitEvent(STD, g_sc.evP, 0);

    for (int l = 0; l < 2; l++) {
        layernorm_k<<<BT, 256, 0, STD>>>(
            p_h,
            l ? p_o : nullptr, l ? p_o + (size_t)BT * DM : nullptr,
            ln_w + l * DM, ln_b + l * DM, nullptr, p_hn16, 1);
        cudaEventRecord(g_sc.evL[l], STD);

        // ---- d0 on S0 (both in_projs run concurrently)
        cudaStreamWaitEvent(S0, g_sc.evL[l], 0);
        cudaStreamWaitEvent(S0, g_sc.evCI[l * 2 + 0], 0);
        tgemm_k<<<dim3((DPJ + 127) / 128, BT / 128), 256, TG_SMEM, S0>>>(
            p_hn16,
            p_wih + (size_t)(l * 2 + 0) * DPJ * DM,
            p_wil + (size_t)(l * 2 + 0) * DPJ * DM,
            in_proj_b + (size_t)(l * 2 + 0) * DPJ,
            p_zx, DPJ, DM);
        convdt_k<<<NCONV + NDT, 256, 0, S0>>>(conv_w, conv_b, dt_bias, A_log, l, 0);
        scan1_k<<<96 * NCH, HD, 0, S0>>>(Dp, l, 0);
        scan2_k<<<96, HD * DS, 0, S0>>>(0);
        scan3_k<<<96 * NCH, HD, 0, S0>>>(0);
        gated_rms_k<<<BT, 256, 0, S0>>>(ssm_w, l, 0);

        // ---- d1 on S1 (concurrent with d0)
        cudaStreamWaitEvent(S1, g_sc.evL[l], 0);
        cudaStreamWaitEvent(S1, g_sc.evCI[l * 2 + 1], 0);
        tgemm_k<<<dim3((DPJ + 127) / 128, BT / 128), 256, TG_SMEM, S1>>>(
            p_hn16,
            p_wih + (size_t)(l * 2 + 1) * DPJ * DM,
            p_wil + (size_t)(l * 2 + 1) * DPJ * DM,
            in_proj_b + (size_t)(l * 2 + 1) * DPJ,
            p_zx + (size_t)BT * DPJ, DPJ, DM);
        convdt_k<<<NCONV + NDT, 256, 0, S1>>>(conv_w, conv_b, dt_bias, A_log, l, 1);
        scan1_k<<<96 * NCH, HD, 0, S1>>>(Dp, l, 1);
        scan2_k<<<96, HD * DS, 0, S1>>>(1);
        scan3_k<<<96 * NCH, HD, 0, S1>>>(1);
        gated_rms_k<<<BT, 256, 0, S1>>>(ssm_w, l, 1);

        // ---- out_proj d0 (after its own chain only)
        cudaStreamWaitEvent(S0, g_sc.evCO[l * 2 + 0], 0);
        tgemm_k<<<dim3(DM / 128, BT / 128), 256, TG_SMEM, S0>>>(
            p_yn16,
            p_woh + (size_t)(l * 2 + 0) * DM * DI,
            p_wol + (size_t)(l * 2 + 0) * DM * DI,
            nullptr, p_o, DM, DI);
        cudaEventRecord(g_sc.evA[l], S0);

        // ---- out_proj d1
        cudaStreamWaitEvent(S1, g_sc.evCO[l * 2 + 1], 0);
        tgemm_k<<<dim3(DM / 128, BT / 128), 256, TG_SMEM, S1>>>(
            p_yn16 + (size_t)BT * DI,
            p_woh + (size_t)(l * 2 + 1) * DM * DI,
            p_wol + (size_t)(l * 2 + 1) * DM * DI,
            nullptr, p_o + (size_t)BT * DM, DM, DI);
        cudaEventRecord(g_sc.evB[l], S1);

        cudaStreamWaitEvent(STD, g_sc.evA[l], 0);
        cudaStreamWaitEvent(STD, g_sc.evB[l], 0);
    }

    // outputs: hidden = LN(h + o0 + o1, final); pred = hidden16 @ proj_out + b
    const int PRED = BT * DIN, HID = BT * DM;
    float* predp = nullptr;
    float* hidp  = nullptr;
    if (out_size >= PRED + HID)      { predp = out; hidp = out + PRED; }
    else if (out_size == PRED)       { predp = out; }
    else                             { hidp = out; }

    layernorm_k<<<BT, 256, 0, STD>>>(
        p_h, p_o, p_o + (size_t)BT * DM,
        fn_w, fn_b, hidp ? hidp : p_hn, p_hn16, 0);
    if (predp) {
        cudaStreamWaitEvent(STD, g_sc.evPO, 0);
        tgemm_k<<<dim3((DIN + 127) / 128, BT / 128), 256, TG_SMEM, STD>>>(
            p_hn16, p_wpoh, p_wpol, proj_out_b, predp, DIN, DM);
    }
}